// round 2
// baseline (speedup 1.0000x reference)
#include <cuda_runtime.h>

#define N_NODES 4096
#define C_IN    256
#define C_OUT   256
#define BATCH   8
#define M_TOTAL (BATCH * N_NODES)
#define CAP     256   // max nnz per adjacency row (mean ~41)

// ---------------- device scratch (no allocations allowed) ----------------
__device__ float g_dis[2][N_NODES];
__device__ int   g_nnz[2][N_NODES];
__device__ int   g_cj[2][N_NODES][CAP];
__device__ float g_cv[2][N_NODES][CAP];
__device__ float g_prop[N_NODES][2 * C_OUT];      // [propA | propB] per row
__device__ float g_Weff0[C_IN * C_OUT];           // W0a@Wp_top + W0b@Wp_bot
__device__ float g_Weff1[2 * C_OUT * C_OUT];      // [W1a@Wp_top ; W1b@Wp_bot]
__device__ float g_bias[C_OUT];

// ---------------- K1: adjacency pass: degree + CSR compact ---------------
__global__ void __launch_bounds__(256) row_scan(const float* __restrict__ adj1,
                                                const float* __restrict__ adj2)
{
    const int i = blockIdx.x;
    const int a = blockIdx.y;
    const int t = threadIdx.x;
    const float* __restrict__ row = (a == 0 ? adj1 : adj2) + (size_t)i * N_NODES;

    __shared__ int   cnt;
    __shared__ float sdeg[256];
    if (t == 0) cnt = 0;
    __syncthreads();

    float deg = 0.f;
    const float4* r4 = reinterpret_cast<const float4*>(row);
    #pragma unroll
    for (int s = 0; s < 4; s++) {
        int i4 = t + 256 * s;
        float4 v = r4[i4];
        float vv[4] = {v.x, v.y, v.z, v.w};
        int jb = i4 * 4;
        #pragma unroll
        for (int e = 0; e < 4; e++) {
            int j = jb + e;
            float val = vv[e];
            if (j != i && val != 0.f) {
                deg += val;
                int p = atomicAdd(&cnt, 1);
                if (p < CAP) { g_cj[a][i][p] = j; g_cv[a][i][p] = val; }
            }
        }
    }
    sdeg[t] = deg;
    __syncthreads();
    for (int s = 128; s > 0; s >>= 1) {
        if (t < s) sdeg[t] += sdeg[t + s];
        __syncthreads();
    }
    if (t == 0) {
        float d = sdeg[0];
        g_dis[a][i] = (d > 0.f) ? rsqrtf(d) : 0.f;
        g_nnz[a][i] = min(cnt, CAP);
    }
}

// ---------------- fold_bias: tiny, one block --------------------------
__global__ void __launch_bounds__(256) fold_bias(const float* __restrict__ bca,
                                                 const float* __restrict__ bcb,
                                                 const float* __restrict__ bp,
                                                 const float* __restrict__ Wp)
{
    const int o = threadIdx.x;
    float acc = bp[o];
    #pragma unroll 8
    for (int k = 0; k < 256; k++)
        acc += bca[k] * Wp[k * 256 + o] + bcb[k] * Wp[(256 + k) * 256 + o];
    g_bias[o] = acc;
}

// ---------------- K3: sparse propagation prop = -(Ahat @ x[:N]) ----------
__global__ void __launch_bounds__(256) prop_kernel(const float* __restrict__ x)
{
    const int i = blockIdx.x;
    const int a = blockIdx.y;
    const int t = threadIdx.x;

    __shared__ int   sj[CAP];
    __shared__ float sv[CAP];
    const int nnz = g_nnz[a][i];
    for (int e = t; e < nnz; e += 256) {
        int j = g_cj[a][i][e];
        sj[e] = j;
        sv[e] = g_cv[a][i][e] * g_dis[a][j];
    }
    __syncthreads();

    float acc = 0.f;
    for (int e = 0; e < nnz; e++)
        acc += sv[e] * x[(size_t)sj[e] * C_IN + t];

    g_prop[i][a * C_OUT + t] = -g_dis[a][i] * acc;
}

// ---------------- SIMT fp32 tiled GEMM (used for fp32 weight folding) ----
template <int BM, int BN, int BK, int TM, int TN>
__global__ void __launch_bounds__(256) gemm_f32(float* __restrict__ C,
                                                const float* __restrict__ A,
                                                const float* __restrict__ B,
                                                int K, int lda, int ldb, int ldc,
                                                const float* __restrict__ bias,
                                                int accumulate)
{
    __shared__ float As[BK][BM];
    __shared__ float Bs[BK][BN];

    const int tid = threadIdx.x;
    const int rowBase = blockIdx.x * BM;
    const int colBase = blockIdx.y * BN;
    const int tx = tid & 15;
    const int ty = tid >> 4;

    float acc[TM][TN];
    #pragma unroll
    for (int i = 0; i < TM; i++)
        #pragma unroll
        for (int j = 0; j < TN; j++) acc[i][j] = 0.f;

    for (int k0 = 0; k0 < K; k0 += BK) {
        #pragma unroll
        for (int l = 0; l < (BM * BK) / 1024; l++) {
            int idx = tid + l * 256;
            int ar = idx >> 2;
            int ac = (idx & 3) << 2;
            float4 av = *reinterpret_cast<const float4*>(
                &A[(size_t)(rowBase + ar) * lda + k0 + ac]);
            As[ac + 0][ar] = av.x;
            As[ac + 1][ar] = av.y;
            As[ac + 2][ar] = av.z;
            As[ac + 3][ar] = av.w;
        }
        #pragma unroll
        for (int l = 0; l < (BK * BN) / 1024; l++) {
            int idx = tid + l * 256;
            int br = idx >> 4;
            int bc = (idx & 15) << 2;
            *reinterpret_cast<float4*>(&Bs[br][bc]) =
                *reinterpret_cast<const float4*>(&B[(size_t)(k0 + br) * ldb + colBase + bc]);
        }
        __syncthreads();

        #pragma unroll
        for (int k = 0; k < BK; k++) {
            float ra[TM], rb[TN];
            #pragma unroll
            for (int i = 0; i < TM; i++) ra[i] = As[k][ty * TM + i];
            #pragma unroll
            for (int j = 0; j < TN; j++) rb[j] = Bs[k][tx * TN + j];
            #pragma unroll
            for (int i = 0; i < TM; i++)
                #pragma unroll
                for (int j = 0; j < TN; j++)
                    acc[i][j] += ra[i] * rb[j];
        }
        __syncthreads();
    }

    #pragma unroll
    for (int i = 0; i < TM; i++) {
        int r = rowBase + ty * TM + i;
        #pragma unroll
        for (int j = 0; j < TN; j++) {
            int c = colBase + tx * TN + j;
            float v = acc[i][j];
            if (bias) v += bias[c];
            size_t off = (size_t)r * ldc + c;
            if (accumulate) C[off] += v;
            else            C[off] = v;
        }
    }
}

// ---------------- tensor-core tf32 3x GEMM -------------------------------
__device__ __forceinline__ unsigned f2tf(float f) {
    unsigned r;
    asm("cvt.rna.tf32.f32 %0, %1;" : "=r"(r) : "f"(f));
    return r;
}

#define MMA_TF32(d, a, b)                                                   \
    asm volatile("mma.sync.aligned.m16n8k8.row.col.f32.tf32.tf32.f32 "      \
                 "{%0,%1,%2,%3}, {%4,%5,%6,%7}, {%8,%9}, {%0,%1,%2,%3};\n"  \
                 : "+f"((d)[0]), "+f"((d)[1]), "+f"((d)[2]), "+f"((d)[3])   \
                 : "r"((a)[0]), "r"((a)[1]), "r"((a)[2]), "r"((a)[3]),      \
                   "r"((b)[0]), "r"((b)[1]))

// BM=128, BN=64, BK=16; 256 threads = 8 warps as 2(M) x 4(N); warp tile 64x16.
// 3xTF32: D = Ah*Bh + Al*Bh + Ah*Bl  (rel err ~1e-7 per product)
__global__ void __launch_bounds__(256) gemm_tf32_3x(float* __restrict__ C,
                                                    const float* __restrict__ A,
                                                    const float* __restrict__ B,
                                                    int K, int lda, int ldb, int ldc,
                                                    const float* __restrict__ bias,
                                                    int accumulate)
{
    constexpr int BM = 128, BN = 64, BK = 16;
    constexpr int AST = BK + 4;   // 20: conflict-free A-frag loads
    constexpr int BST = BN + 8;   // 72: conflict-free B-frag loads
    __shared__ unsigned Ah[BM][AST], Al[BM][AST];
    __shared__ unsigned Bh[BK][BST], Bl[BK][BST];

    const int tid  = threadIdx.x;
    const int warp = tid >> 5, lane = tid & 31;
    const int grp  = lane >> 2, quad = lane & 3;
    const int wm   = (warp & 1) * 64;
    const int wn   = (warp >> 1) * 16;
    const int rowBase = blockIdx.x * BM;
    const int colBase = blockIdx.y * BN;

    float acc[4][2][4];
    #pragma unroll
    for (int mt = 0; mt < 4; mt++)
        #pragma unroll
        for (int nt = 0; nt < 2; nt++)
            #pragma unroll
            for (int e = 0; e < 4; e++) acc[mt][nt][e] = 0.f;

    for (int k0 = 0; k0 < K; k0 += BK) {
        // --- load A tile (BM x BK), split hi/lo ---
        #pragma unroll
        for (int l = 0; l < 2; l++) {
            int f4 = tid + l * 256;            // 0..511
            int m  = f4 >> 2;
            int kc = (f4 & 3) << 2;
            float4 v = *reinterpret_cast<const float4*>(
                &A[(size_t)(rowBase + m) * lda + k0 + kc]);
            float vv[4] = {v.x, v.y, v.z, v.w};
            #pragma unroll
            for (int e = 0; e < 4; e++) {
                unsigned h = f2tf(vv[e]);
                Ah[m][kc + e] = h;
                Al[m][kc + e] = f2tf(vv[e] - __uint_as_float(h));
            }
        }
        // --- load B tile (BK x BN), split hi/lo ---
        {
            int k = tid >> 4;
            int n = (tid & 15) << 2;
            float4 v = *reinterpret_cast<const float4*>(
                &B[(size_t)(k0 + k) * ldb + colBase + n]);
            float vv[4] = {v.x, v.y, v.z, v.w};
            #pragma unroll
            for (int e = 0; e < 4; e++) {
                unsigned h = f2tf(vv[e]);
                Bh[k][n + e] = h;
                Bl[k][n + e] = f2tf(vv[e] - __uint_as_float(h));
            }
        }
        __syncthreads();

        #pragma unroll
        for (int ks = 0; ks < BK; ks += 8) {
            unsigned ah[4][4], al[4][4], bh[2][2], bl[2][2];
            #pragma unroll
            for (int mt = 0; mt < 4; mt++) {
                int mr = wm + mt * 16 + grp;
                ah[mt][0] = Ah[mr][ks + quad];
                ah[mt][1] = Ah[mr + 8][ks + quad];
                ah[mt][2] = Ah[mr][ks + quad + 4];
                ah[mt][3] = Ah[mr + 8][ks + quad + 4];
                al[mt][0] = Al[mr][ks + quad];
                al[mt][1] = Al[mr + 8][ks + quad];
                al[mt][2] = Al[mr][ks + quad + 4];
                al[mt][3] = Al[mr + 8][ks + quad + 4];
            }
            #pragma unroll
            for (int nt = 0; nt < 2; nt++) {
                int nc = wn + nt * 8 + grp;
                bh[nt][0] = Bh[ks + quad][nc];
                bh[nt][1] = Bh[ks + quad + 4][nc];
                bl[nt][0] = Bl[ks + quad][nc];
                bl[nt][1] = Bl[ks + quad + 4][nc];
            }
            #pragma unroll
            for (int mt = 0; mt < 4; mt++)
                #pragma unroll
                for (int nt = 0; nt < 2; nt++) {
                    MMA_TF32(acc[mt][nt], ah[mt], bh[nt]);
                    MMA_TF32(acc[mt][nt], al[mt], bh[nt]);
                    MMA_TF32(acc[mt][nt], ah[mt], bl[nt]);
                }
        }
        __syncthreads();
    }

    // --- epilogue ---
    #pragma unroll
    for (int mt = 0; mt < 4; mt++) {
        int r0 = rowBase + wm + mt * 16 + grp;
        #pragma unroll
        for (int nt = 0; nt < 2; nt++) {
            int c = colBase + wn + nt * 8 + 2 * quad;
            float b0 = 0.f, b1 = 0.f;
            if (bias) { b0 = bias[c]; b1 = bias[c + 1]; }
            float2* p0 = reinterpret_cast<float2*>(&C[(size_t)r0 * ldc + c]);
            float2* p1 = reinterpret_cast<float2*>(&C[(size_t)(r0 + 8) * ldc + c]);
            float2 v0 = make_float2(acc[mt][nt][0] + b0, acc[mt][nt][1] + b1);
            float2 v1 = make_float2(acc[mt][nt][2] + b0, acc[mt][nt][3] + b1);
            if (accumulate) {
                float2 o0 = *p0, o1 = *p1;
                v0.x += o0.x; v0.y += o0.y;
                v1.x += o1.x; v1.y += o1.y;
            }
            *p0 = v0;
            *p1 = v1;
        }
    }
}

// ---------------- launcher ----------------
extern "C" void kernel_launch(void* const* d_in, const int* in_sizes, int n_in,
                              void* d_out, int out_size)
{
    const float* x    = (const float*)d_in[0];
    const float* adj1 = (const float*)d_in[1];
    const float* adj2 = (const float*)d_in[2];
    const float* W0a  = (const float*)d_in[3];
    const float* W1a  = (const float*)d_in[4];
    const float* bca  = (const float*)d_in[5];
    const float* W0b  = (const float*)d_in[6];
    const float* W1b  = (const float*)d_in[7];
    const float* bcb  = (const float*)d_in[8];
    const float* Wp   = (const float*)d_in[9];
    const float* bp   = (const float*)d_in[10];
    float* out = (float*)d_out;

    float *p_prop, *p_W0, *p_W1, *p_bias;
    cudaGetSymbolAddress((void**)&p_prop, g_prop);
    cudaGetSymbolAddress((void**)&p_W0,   g_Weff0);
    cudaGetSymbolAddress((void**)&p_W1,   g_Weff1);
    cudaGetSymbolAddress((void**)&p_bias, g_bias);

    const float* Wp_top = Wp;
    const float* Wp_bot = Wp + 256 * 256;

    // 1. adjacency pass: degrees + CSR compaction
    row_scan<<<dim3(N_NODES, 2), 256>>>(adj1, adj2);

    // 2. fold projection into Cheb weights (fp32, smem-tiled GEMMs)
    gemm_f32<64, 64, 16, 4, 4><<<dim3(4, 4), 256>>>(
        p_W0, W0a, Wp_top, 256, 256, 256, 256, nullptr, 0);
    gemm_f32<64, 64, 16, 4, 4><<<dim3(4, 4), 256>>>(
        p_W0, W0b, Wp_bot, 256, 256, 256, 256, nullptr, 1);
    gemm_f32<64, 64, 16, 4, 4><<<dim3(4, 4), 256>>>(
        p_W1, W1a, Wp_top, 256, 256, 256, 256, nullptr, 0);
    gemm_f32<64, 64, 16, 4, 4><<<dim3(4, 4), 256>>>(
        p_W1 + 256 * 256, W1b, Wp_bot, 256, 256, 256, 256, nullptr, 0);
    fold_bias<<<1, 256>>>(bca, bcb, bp, Wp);

    // 3. sparse propagation
    prop_kernel<<<dim3(N_NODES, 2), 256>>>(x);

    // 4. out = x_flat @ Weff0 + bias      [32768 x 256 x 256] (tensor cores)
    gemm_tf32_3x<<<dim3(M_TOTAL / 128, C_OUT / 64), 256>>>(
        out, x, p_W0, C_IN, C_IN, C_OUT, C_OUT, p_bias, 0);

    // 5. out[:4096] += [propA|propB] @ Weff1   [4096 x 256 x 512] (tensor cores)
    gemm_tf32_3x<<<dim3(N_NODES / 128, C_OUT / 64), 256>>>(
        out, p_prop, p_W1, 2 * C_OUT, 2 * C_OUT, C_OUT, C_OUT, nullptr, 1);
}

// round 5
// speedup vs baseline: 1.6237x; 1.6237x over previous
#include <cuda_runtime.h>
#include <cuda_bf16.h>
#include <cstdint>

#define N_NODES 4096
#define C_IN    256
#define C_OUT   256
#define BATCH   8
#define M_TOTAL (BATCH * N_NODES)
#define CAP     256

// ---------------- device scratch ----------------
__device__ float g_dis[2][N_NODES];
__device__ int   g_nnz[2][N_NODES];
__device__ int   g_cj[2][N_NODES][CAP];
__device__ float g_cv[2][N_NODES][CAP];
__device__ float g_prop[N_NODES][2 * C_OUT];     // [propA | propB]
__device__ float g_Weff0[C_IN * C_OUT];          // [K=256][N=256]
__device__ float g_Weff1[2 * C_OUT * C_OUT];     // [K=512][N=256]
__device__ float g_bias[C_OUT];
// bf16 2-way splits of Weff, transposed to [N][K] (mma .col B layout)
__device__ unsigned short g_B0h[C_OUT * C_IN],      g_B0l[C_OUT * C_IN];
__device__ unsigned short g_B1h[C_OUT * 2 * C_OUT], g_B1l[C_OUT * 2 * C_OUT];

__device__ __forceinline__ uint32_t smem_u32(const void* p) {
    uint32_t a;
    asm("{ .reg .u64 t; cvta.to.shared.u64 t, %1; cvt.u32.u64 %0, t; }" : "=r"(a) : "l"(p));
    return a;
}

// ---------------- K1: adjacency pass: degree + CSR compact ---------------
__global__ void __launch_bounds__(256) row_scan(const float* __restrict__ adj1,
                                                const float* __restrict__ adj2)
{
    const int i = blockIdx.x, a = blockIdx.y, t = threadIdx.x;
    const float* __restrict__ row = (a == 0 ? adj1 : adj2) + (size_t)i * N_NODES;
    __shared__ int cnt;
    __shared__ float sdeg[256];
    if (t == 0) cnt = 0;
    __syncthreads();
    float deg = 0.f;
    const float4* r4 = reinterpret_cast<const float4*>(row);
    #pragma unroll
    for (int s = 0; s < 4; s++) {
        int i4 = t + 256 * s;
        float4 v = r4[i4];
        float vv[4] = {v.x, v.y, v.z, v.w};
        int jb = i4 * 4;
        #pragma unroll
        for (int e = 0; e < 4; e++) {
            int j = jb + e;
            float val = vv[e];
            if (j != i && val != 0.f) {
                deg += val;
                int p = atomicAdd(&cnt, 1);
                if (p < CAP) { g_cj[a][i][p] = j; g_cv[a][i][p] = val; }
            }
        }
    }
    sdeg[t] = deg;
    __syncthreads();
    for (int s = 128; s > 0; s >>= 1) {
        if (t < s) sdeg[t] += sdeg[t + s];
        __syncthreads();
    }
    if (t == 0) {
        float d = sdeg[0];
        g_dis[a][i] = (d > 0.f) ? rsqrtf(d) : 0.f;
        g_nnz[a][i] = min(cnt, CAP);
    }
}

// ---------------- K2: batched weight folding (one launch) ----------------
__global__ void __launch_bounds__(256) fold_all(const float* __restrict__ W0a,
                                                const float* __restrict__ W1a,
                                                const float* __restrict__ W0b,
                                                const float* __restrict__ W1b,
                                                const float* __restrict__ Wp)
{
    constexpr int BK = 16;
    __shared__ float As[BK][64];
    __shared__ float Bs[BK][64];

    const int job = blockIdx.z;
    const float *A1, *B1, *A2 = nullptr, *B2 = nullptr;
    float* C;
    if (job == 0)      { A1 = W0a; B1 = Wp;         A2 = W0b; B2 = Wp + 65536; C = g_Weff0; }
    else if (job == 1) { A1 = W1a; B1 = Wp;         C = g_Weff1; }
    else               { A1 = W1b; B1 = Wp + 65536; C = g_Weff1 + 65536; }

    const int tid = threadIdx.x;
    const int rowBase = blockIdx.x * 64, colBase = blockIdx.y * 64;
    const int tx = tid & 15, ty = tid >> 4;

    float acc[4][4];
    #pragma unroll
    for (int i = 0; i < 4; i++)
        #pragma unroll
        for (int j = 0; j < 4; j++) acc[i][j] = 0.f;

    for (int pass = 0; pass < 2; pass++) {
        const float* A = pass ? A2 : A1;
        const float* B = pass ? B2 : B1;
        if (!A) break;
        for (int k0 = 0; k0 < 256; k0 += BK) {
            {
                int ar = tid >> 2, ac = (tid & 3) << 2;
                float4 av = *reinterpret_cast<const float4*>(&A[(size_t)(rowBase + ar) * 256 + k0 + ac]);
                As[ac + 0][ar] = av.x; As[ac + 1][ar] = av.y;
                As[ac + 2][ar] = av.z; As[ac + 3][ar] = av.w;
            }
            {
                int br = tid >> 4, bc = (tid & 15) << 2;
                *reinterpret_cast<float4*>(&Bs[br][bc]) =
                    *reinterpret_cast<const float4*>(&B[(size_t)(k0 + br) * 256 + colBase + bc]);
            }
            __syncthreads();
            #pragma unroll
            for (int k = 0; k < BK; k++) {
                float ra[4], rb[4];
                #pragma unroll
                for (int i = 0; i < 4; i++) ra[i] = As[k][ty * 4 + i];
                #pragma unroll
                for (int j = 0; j < 4; j++) rb[j] = Bs[k][tx * 4 + j];
                #pragma unroll
                for (int i = 0; i < 4; i++)
                    #pragma unroll
                    for (int j = 0; j < 4; j++) acc[i][j] += ra[i] * rb[j];
            }
            __syncthreads();
        }
    }
    #pragma unroll
    for (int i = 0; i < 4; i++)
        #pragma unroll
        for (int j = 0; j < 4; j++)
            C[(size_t)(rowBase + ty * 4 + i) * 256 + colBase + tx * 4 + j] = acc[i][j];
}

__global__ void __launch_bounds__(256) fold_bias(const float* __restrict__ bca,
                                                 const float* __restrict__ bcb,
                                                 const float* __restrict__ bp,
                                                 const float* __restrict__ Wp)
{
    const int o = threadIdx.x;
    float acc = bp[o];
    #pragma unroll 8
    for (int k = 0; k < 256; k++)
        acc += bca[k] * Wp[k * 256 + o] + bcb[k] * Wp[(256 + k) * 256 + o];
    g_bias[o] = acc;
}

// ---------------- K3: split Weff -> bf16 h/l pairs, transposed [N][K] ----
__global__ void __launch_bounds__(256) split_w()
{
    const int which = blockIdx.y;
    const int K = which ? 512 : 256;
    const int total = 256 * K;
    int idx = blockIdx.x * 256 + threadIdx.x;
    if (idx >= total) return;
    int n = idx / K, k = idx - n * K;
    const float* W = which ? g_Weff1 : g_Weff0;
    float v = W[(size_t)k * 256 + n];
    __nv_bfloat16 h = __float2bfloat16_rn(v);
    __nv_bfloat16 l = __float2bfloat16_rn(v - __bfloat162float(h));
    if (which) { g_B1h[idx] = __bfloat16_as_ushort(h); g_B1l[idx] = __bfloat16_as_ushort(l); }
    else       { g_B0h[idx] = __bfloat16_as_ushort(h); g_B0l[idx] = __bfloat16_as_ushort(l); }
}

// ---------------- K4: sparse propagation prop = -(Ahat @ x[:N]) ----------
__global__ void __launch_bounds__(256) prop_kernel(const float* __restrict__ x)
{
    const int i = blockIdx.x, a = blockIdx.y, t = threadIdx.x;
    __shared__ int   sj[CAP];
    __shared__ float sv[CAP];
    const int nnz = g_nnz[a][i];
    for (int e = t; e < nnz; e += 256) {
        int j = g_cj[a][i][e];
        sj[e] = j;
        sv[e] = g_cv[a][i][e] * g_dis[a][j];
    }
    __syncthreads();
    float acc = 0.f;
    for (int e = 0; e < nnz; e++)
        acc += sv[e] * x[(size_t)sj[e] * C_IN + t];
    g_prop[i][a * C_OUT + t] = -g_dis[a][i] * acc;
}

// ---------------- K5: fused bf16 mma.sync GEMM ---------------------------
// out[m][n] = bias[n] + x[m]@Weff0[:,n]  (+ prop[m]@Weff1[:,n] for m<4096)
// 2-way bf16 split: D = Ah*Bh + Ah*Bl + Al*Bh  (error ~2^-18 per product)
// CTA 128x64, BK=32, 8 warps as 2(M) x 4(N); warp tile 64x16.

#define LDM_X4(r0, r1, r2, r3, a) \
    asm volatile("ldmatrix.sync.aligned.m8n8.x4.shared.b16 {%0,%1,%2,%3}, [%4];" \
                 : "=r"(r0), "=r"(r1), "=r"(r2), "=r"(r3) : "r"(a))
#define LDM_X2(r0, r1, a) \
    asm volatile("ldmatrix.sync.aligned.m8n8.x2.shared.b16 {%0,%1}, [%2];" \
                 : "=r"(r0), "=r"(r1) : "r"(a))
#define MMA_BF16(d, a, b) \
    asm volatile("mma.sync.aligned.m16n8k16.row.col.f32.bf16.bf16.f32 " \
                 "{%0,%1,%2,%3}, {%4,%5,%6,%7}, {%8,%9}, {%0,%1,%2,%3};" \
                 : "+f"((d)[0]), "+f"((d)[1]), "+f"((d)[2]), "+f"((d)[3]) \
                 : "r"((a)[0]), "r"((a)[1]), "r"((a)[2]), "r"((a)[3]),   \
                   "r"((b)[0]), "r"((b)[1]))

// smem: Ah[128 rows x 80B] @0, Al @10240, Bh[64 x 80B] @20480, Bl @25600
__global__ void __launch_bounds__(256, 2) gemm_mma(float* __restrict__ out,
                                                   const float* __restrict__ x)
{
    __shared__ __align__(16) unsigned char sm[30720];
    char* smp = reinterpret_cast<char*>(sm);
    const uint32_t sb = smem_u32(sm);

    const int tid = threadIdx.x, warp = tid >> 5, lane = tid & 31;
    const int rowBase = blockIdx.x * 128;
    const int colBase = blockIdx.y * 64;
    const int m0 = (warp & 1) * 64;
    const int n0 = (warp >> 1) * 16;
    const int nch = (rowBase < N_NODES) ? 24 : 8;

    // per-lane ldmatrix base addresses (80B padded rows, conflict-free)
    const uint32_t aBase = sb + (uint32_t)(m0 + (lane & 15)) * 80u + ((lane >> 4) << 4);
    const uint32_t bBase = sb + 20480u + (uint32_t)(n0 + (lane & 7)) * 80u + (((lane >> 3) & 1) << 4);

    float acc[4][2][4];
    #pragma unroll
    for (int mb = 0; mb < 4; mb++)
        #pragma unroll
        for (int nb = 0; nb < 2; nb++)
            #pragma unroll
            for (int e = 0; e < 4; e++) acc[mb][nb][e] = 0.f;

    for (int ch = 0; ch < nch; ch++) {
        // ---- A: fp32 -> bf16 h/l split into smem ----
        const float* Asrc;
        int strideA;
        if (ch < 8) { Asrc = x + (size_t)rowBase * C_IN + ch * 32;                  strideA = C_IN; }
        else        { Asrc = &g_prop[0][0] + (size_t)rowBase * 512 + (ch - 8) * 32; strideA = 512; }
        #pragma unroll
        for (int i = 0; i < 4; i++) {
            int flat = tid + 256 * i;          // 0..1023 float4 slots
            int r = flat >> 3, c4 = flat & 7;  // row, float4-within-row
            float4 v = *reinterpret_cast<const float4*>(Asrc + (size_t)r * strideA + c4 * 4);
            __nv_bfloat162 h01 = __floats2bfloat162_rn(v.x, v.y);
            __nv_bfloat162 h23 = __floats2bfloat162_rn(v.z, v.w);
            float2 f01 = __bfloat1622float2(h01);
            float2 f23 = __bfloat1622float2(h23);
            __nv_bfloat162 l01 = __floats2bfloat162_rn(v.x - f01.x, v.y - f01.y);
            __nv_bfloat162 l23 = __floats2bfloat162_rn(v.z - f23.x, v.w - f23.y);
            int off = r * 80 + c4 * 8;
            *reinterpret_cast<uint2*>(smp + off) =
                make_uint2(*reinterpret_cast<unsigned*>(&h01), *reinterpret_cast<unsigned*>(&h23));
            *reinterpret_cast<uint2*>(smp + 10240 + off) =
                make_uint2(*reinterpret_cast<unsigned*>(&l01), *reinterpret_cast<unsigned*>(&l23));
        }
        // ---- B: copy pre-split bf16 tiles (64 rows x 64B each) ----
        {
            const unsigned short *Bh_src, *Bl_src;
            int Kb, kk;
            if (ch < 8) { Bh_src = g_B0h; Bl_src = g_B0l; Kb = 256; kk = ch * 32; }
            else        { Bh_src = g_B1h; Bl_src = g_B1l; Kb = 512; kk = (ch - 8) * 32; }
            int r = tid >> 2, seg = tid & 3;   // 64 rows x 4 segs of 16B = 256 threads
            size_t goff = (size_t)(colBase + r) * Kb + kk + seg * 8;
            int soff = r * 80 + seg * 16;
            *reinterpret_cast<uint4*>(smp + 20480 + soff) =
                *reinterpret_cast<const uint4*>(Bh_src + goff);
            *reinterpret_cast<uint4*>(smp + 25600 + soff) =
                *reinterpret_cast<const uint4*>(Bl_src + goff);
        }
        __syncthreads();

        // ---- compute: 2 k16-steps per chunk ----
        #pragma unroll
        for (int ks = 0; ks < 32; ks += 16) {
            unsigned ah[4][4], al[4][4], bh[2][2], bl[2][2];
            #pragma unroll
            for (int mb = 0; mb < 4; mb++) {
                uint32_t a = aBase + mb * (16 * 80) + ks * 2;
                LDM_X4(ah[mb][0], ah[mb][1], ah[mb][2], ah[mb][3], a);
                LDM_X4(al[mb][0], al[mb][1], al[mb][2], al[mb][3], a + 10240u);
            }
            #pragma unroll
            for (int nb = 0; nb < 2; nb++) {
                uint32_t b = bBase + nb * (8 * 80) + ks * 2;
                LDM_X2(bh[nb][0], bh[nb][1], b);
                LDM_X2(bl[nb][0], bl[nb][1], b + 5120u);
            }
            #pragma unroll
            for (int mb = 0; mb < 4; mb++)
                #pragma unroll
                for (int nb = 0; nb < 2; nb++) {
                    MMA_BF16(acc[mb][nb], ah[mb], bh[nb]);
                    MMA_BF16(acc[mb][nb], ah[mb], bl[nb]);
                    MMA_BF16(acc[mb][nb], al[mb], bh[nb]);
                }
        }
        __syncthreads();
    }

    // ---- epilogue: acc + bias -> out ----
    const int g = lane >> 2, t = lane & 3;
    #pragma unroll
    for (int mb = 0; mb < 4; mb++) {
        int r0 = rowBase + m0 + mb * 16 + g;
        #pragma unroll
        for (int nb = 0; nb < 2; nb++) {
            int c = colBase + n0 + nb * 8 + 2 * t;
            float b0 = g_bias[c], b1 = g_bias[c + 1];
            *reinterpret_cast<float2*>(&out[(size_t)r0 * C_OUT + c]) =
                make_float2(acc[mb][nb][0] + b0, acc[mb][nb][1] + b1);
            *reinterpret_cast<float2*>(&out[(size_t)(r0 + 8) * C_OUT + c]) =
                make_float2(acc[mb][nb][2] + b0, acc[mb][nb][3] + b1);
        }
    }
}

// ---------------- launcher ----------------
extern "C" void kernel_launch(void* const* d_in, const int* in_sizes, int n_in,
                              void* d_out, int out_size)
{
    const float* x    = (const float*)d_in[0];
    const float* adj1 = (const float*)d_in[1];
    const float* adj2 = (const float*)d_in[2];
    const float* W0a  = (const float*)d_in[3];
    const float* W1a  = (const float*)d_in[4];
    const float* bca  = (const float*)d_in[5];
    const float* W0b  = (const float*)d_in[6];
    const float* W1b  = (const float*)d_in[7];
    const float* bcb  = (const float*)d_in[8];
    const float* Wp   = (const float*)d_in[9];
    const float* bp   = (const float*)d_in[10];
    float* out = (float*)d_out;

    // 1. adjacency pass
    row_scan<<<dim3(N_NODES, 2), 256>>>(adj1, adj2);
    // 2. fold projection into Cheb weights (one batched launch) + bias
    fold_all<<<dim3(4, 4, 3), 256>>>(W0a, W1a, W0b, W1b, Wp);
    fold_bias<<<1, 256>>>(bca, bcb, bp, Wp);
    // 3. split folded weights into bf16 h/l ([N][K] layout)
    split_w<<<dim3(512, 2), 256>>>();
    // 4. sparse propagation
    prop_kernel<<<dim3(N_NODES, 2), 256>>>(x);
    // 5. fused bf16 tensor-core GEMM
    gemm_mma<<<dim3(M_TOTAL / 128, C_OUT / 64), 256>>>(out, x);
}

// round 7
// speedup vs baseline: 1.7488x; 1.0771x over previous
#include <cuda_runtime.h>
#include <cuda_bf16.h>
#include <cstdint>

#define N_NODES 4096
#define C_IN    256
#define C_OUT   256
#define BATCH   8
#define M_TOTAL (BATCH * N_NODES)
#define CAP     256

// ---------------- device scratch ----------------
__device__ float g_dis[2][N_NODES];
__device__ int   g_nnz[2][N_NODES];
__device__ int   g_cj[2][N_NODES][CAP];
__device__ float g_cv[2][N_NODES][CAP];
__device__ float g_bias[C_OUT];
// bf16 h/l splits, A-side ([M][K] row-major) and B-side ([N][K])
__device__ unsigned short g_xh[M_TOTAL * C_IN],  g_xl[M_TOTAL * C_IN];    // x split
__device__ unsigned short g_ph[N_NODES * 512],   g_pl[N_NODES * 512];     // prop split
__device__ unsigned short g_B0h[C_OUT * C_IN],      g_B0l[C_OUT * C_IN];
__device__ unsigned short g_B1h[C_OUT * 2 * C_OUT], g_B1l[C_OUT * 2 * C_OUT];

__device__ __forceinline__ uint32_t smem_u32(const void* p) {
    uint32_t a;
    asm("{ .reg .u64 t; cvta.to.shared.u64 t, %1; cvt.u32.u64 %0, t; }" : "=r"(a) : "l"(p));
    return a;
}

// =================== L1 mega kernel ===================
// blocks [0,8192): row_scan;  [8192,8240): fold (48);  8240: bias;
// [8241, 8241+8192): x pre-split.

struct ScanSh { int cnt; float sdeg[256]; };
struct FoldSh { float As[16][64]; float Bs[16][64]; };

__device__ void row_scan_body(char* sh, const float* __restrict__ adj, int i, int a)
{
    ScanSh* s = reinterpret_cast<ScanSh*>(sh);
    const int t = threadIdx.x;
    const float* __restrict__ row = adj + (size_t)i * N_NODES;
    if (t == 0) s->cnt = 0;
    __syncthreads();
    float deg = 0.f;
    const float4* r4 = reinterpret_cast<const float4*>(row);
    #pragma unroll
    for (int ss = 0; ss < 4; ss++) {
        int i4 = t + 256 * ss;
        float4 v = r4[i4];
        float vv[4] = {v.x, v.y, v.z, v.w};
        int jb = i4 * 4;
        #pragma unroll
        for (int e = 0; e < 4; e++) {
            int j = jb + e;
            float val = vv[e];
            if (j != i && val != 0.f) {
                deg += val;
                int p = atomicAdd(&s->cnt, 1);
                if (p < CAP) { g_cj[a][i][p] = j; g_cv[a][i][p] = val; }
            }
        }
    }
    s->sdeg[t] = deg;
    __syncthreads();
    for (int st = 128; st > 0; st >>= 1) {
        if (t < st) s->sdeg[t] += s->sdeg[t + st];
        __syncthreads();
    }
    if (t == 0) {
        float d = s->sdeg[0];
        g_dis[a][i] = (d > 0.f) ? rsqrtf(d) : 0.f;
        g_nnz[a][i] = min(s->cnt, CAP);
    }
}

__device__ void fold_body(char* sh, int fid,
                          const float* __restrict__ W0a, const float* __restrict__ W1a,
                          const float* __restrict__ W0b, const float* __restrict__ W1b,
                          const float* __restrict__ Wp)
{
    FoldSh* s = reinterpret_cast<FoldSh*>(sh);
    const int bx = fid & 3, by = (fid >> 2) & 3, job = fid >> 4;
    const float *A1, *B1, *A2 = nullptr, *B2 = nullptr;
    if (job == 0)      { A1 = W0a; B1 = Wp;         A2 = W0b; B2 = Wp + 65536; }
    else if (job == 1) { A1 = W1a; B1 = Wp; }
    else               { A1 = W1b; B1 = Wp + 65536; }

    const int tid = threadIdx.x;
    const int rowBase = bx * 64, colBase = by * 64;
    const int tx = tid & 15, ty = tid >> 4;

    float acc[4][4];
    #pragma unroll
    for (int i = 0; i < 4; i++)
        #pragma unroll
        for (int j = 0; j < 4; j++) acc[i][j] = 0.f;

    for (int pass = 0; pass < 2; pass++) {
        const float* A = pass ? A2 : A1;
        const float* B = pass ? B2 : B1;
        if (!A) break;
        for (int k0 = 0; k0 < 256; k0 += 16) {
            {
                int ar = tid >> 2, ac = (tid & 3) << 2;
                float4 av = *reinterpret_cast<const float4*>(&A[(size_t)(rowBase + ar) * 256 + k0 + ac]);
                s->As[ac + 0][ar] = av.x; s->As[ac + 1][ar] = av.y;
                s->As[ac + 2][ar] = av.z; s->As[ac + 3][ar] = av.w;
            }
            {
                int br = tid >> 4, bc = (tid & 15) << 2;
                *reinterpret_cast<float4*>(&s->Bs[br][bc]) =
                    *reinterpret_cast<const float4*>(&B[(size_t)(k0 + br) * 256 + colBase + bc]);
            }
            __syncthreads();
            #pragma unroll
            for (int k = 0; k < 16; k++) {
                float ra[4], rb[4];
                #pragma unroll
                for (int i = 0; i < 4; i++) ra[i] = s->As[k][ty * 4 + i];
                #pragma unroll
                for (int j = 0; j < 4; j++) rb[j] = s->Bs[k][tx * 4 + j];
                #pragma unroll
                for (int i = 0; i < 4; i++)
                    #pragma unroll
                    for (int j = 0; j < 4; j++) acc[i][j] += ra[i] * rb[j];
            }
            __syncthreads();
        }
    }
    // direct bf16 h/l split, transposed to [N][K]
    #pragma unroll
    for (int i = 0; i < 4; i++) {
        int kIdx = rowBase + ty * 4 + i;
        #pragma unroll
        for (int j = 0; j < 4; j++) {
            int nIdx = colBase + tx * 4 + j;
            float v = acc[i][j];
            __nv_bfloat16 h = __float2bfloat16_rn(v);
            __nv_bfloat16 l = __float2bfloat16_rn(v - __bfloat162float(h));
            unsigned short hu = __bfloat16_as_ushort(h), lu = __bfloat16_as_ushort(l);
            if (job == 0)      { g_B0h[nIdx * 256 + kIdx] = hu; g_B0l[nIdx * 256 + kIdx] = lu; }
            else if (job == 1) { g_B1h[nIdx * 512 + kIdx] = hu; g_B1l[nIdx * 512 + kIdx] = lu; }
            else               { g_B1h[nIdx * 512 + 256 + kIdx] = hu; g_B1l[nIdx * 512 + 256 + kIdx] = lu; }
        }
    }
}

__device__ void bias_body(const float* __restrict__ bca, const float* __restrict__ bcb,
                          const float* __restrict__ bp,  const float* __restrict__ Wp)
{
    const int o = threadIdx.x;
    float acc = bp[o];
    #pragma unroll 8
    for (int k = 0; k < 256; k++)
        acc += bca[k] * Wp[k * 256 + o] + bcb[k] * Wp[(256 + k) * 256 + o];
    g_bias[o] = acc;
}

__device__ void xsplit_body(const float* __restrict__ x, int bid)
{
    int idx = bid * 1024 + threadIdx.x * 4;       // float4-aligned
    float4 v = *reinterpret_cast<const float4*>(x + idx);
    __nv_bfloat162 h01 = __floats2bfloat162_rn(v.x, v.y);
    __nv_bfloat162 h23 = __floats2bfloat162_rn(v.z, v.w);
    float2 f01 = __bfloat1622float2(h01);
    float2 f23 = __bfloat1622float2(h23);
    __nv_bfloat162 l01 = __floats2bfloat162_rn(v.x - f01.x, v.y - f01.y);
    __nv_bfloat162 l23 = __floats2bfloat162_rn(v.z - f23.x, v.w - f23.y);
    *reinterpret_cast<uint2*>(&g_xh[idx]) =
        make_uint2(*reinterpret_cast<unsigned*>(&h01), *reinterpret_cast<unsigned*>(&h23));
    *reinterpret_cast<uint2*>(&g_xl[idx]) =
        make_uint2(*reinterpret_cast<unsigned*>(&l01), *reinterpret_cast<unsigned*>(&l23));
}

__global__ void __launch_bounds__(256) mega1(const float* __restrict__ x,
                                             const float* __restrict__ adj1,
                                             const float* __restrict__ adj2,
                                             const float* __restrict__ W0a,
                                             const float* __restrict__ W1a,
                                             const float* __restrict__ W0b,
                                             const float* __restrict__ W1b,
                                             const float* __restrict__ Wp,
                                             const float* __restrict__ bca,
                                             const float* __restrict__ bcb,
                                             const float* __restrict__ bp)
{
    __shared__ __align__(16) char sh[sizeof(FoldSh)];
    const int id = blockIdx.x;
    if (id < 8192) {
        row_scan_body(sh, (id < 4096) ? adj1 : adj2, id & 4095, id >> 12);
    } else if (id < 8240) {
        fold_body(sh, id - 8192, W0a, W1a, W0b, W1b, Wp);
    } else if (id == 8240) {
        bias_body(bca, bcb, bp, Wp);
    } else {
        xsplit_body(x, id - 8241);
    }
}

// =================== L2: sparse propagation =======================
// prop[i] = -(Ahat x)[i]; written directly as bf16 h/l into g_ph/g_pl
__global__ void __launch_bounds__(256) prop_kernel(const float* __restrict__ x)
{
    const int i = blockIdx.x, a = blockIdx.y, t = threadIdx.x;
    __shared__ int   sj[CAP];
    __shared__ float sv[CAP];
    const int nnz = g_nnz[a][i];
    for (int e = t; e < nnz; e += 256) {
        int j = g_cj[a][i][e];
        sj[e] = j;
        sv[e] = g_cv[a][i][e] * g_dis[a][j];
    }
    __syncthreads();
    float acc = 0.f;
    for (int e = 0; e < nnz; e++)
        acc += sv[e] * x[(size_t)sj[e] * C_IN + t];
    float val = -g_dis[a][i] * acc;
    __nv_bfloat16 h = __float2bfloat16_rn(val);
    __nv_bfloat16 l = __float2bfloat16_rn(val - __bfloat162float(h));
    size_t off = (size_t)i * 512 + a * 256 + t;
    g_ph[off] = __bfloat16_as_ushort(h);
    g_pl[off] = __bfloat16_as_ushort(l);
}

// =================== L3: fused bf16 mma.sync GEMM =================
// out[m][n] = bias[n] + x[m]@Weff0[:,n] (+ prop[m]@Weff1[:,n] for m<4096)
// D = Ah*Bh + Ah*Bl + Al*Bh ; CTA 128x128, BK=32, warps 2(M)x4(N), warp 64x32.

#define LDM_X4(r0, r1, r2, r3, a) \
    asm volatile("ldmatrix.sync.aligned.m8n8.x4.shared.b16 {%0,%1,%2,%3}, [%4];" \
                 : "=r"(r0), "=r"(r1), "=r"(r2), "=r"(r3) : "r"(a))
#define LDM_X2(r0, r1, a) \
    asm volatile("ldmatrix.sync.aligned.m8n8.x2.shared.b16 {%0,%1}, [%2];" \
                 : "=r"(r0), "=r"(r1) : "r"(a))
#define MMA_BF16(d, a, b) \
    asm volatile("mma.sync.aligned.m16n8k16.row.col.f32.bf16.bf16.f32 " \
                 "{%0,%1,%2,%3}, {%4,%5,%6,%7}, {%8,%9}, {%0,%1,%2,%3};" \
                 : "+f"((d)[0]), "+f"((d)[1]), "+f"((d)[2]), "+f"((d)[3]) \
                 : "r"((a)[0]), "r"((a)[1]), "r"((a)[2]), "r"((a)[3]),   \
                   "r"((b)[0]), "r"((b)[1]))

// smem (80B row stride): Ah @0, Al @10240, Bh @20480, Bl @30720  (40960 B)
__global__ void __launch_bounds__(256, 2) gemm_mma(float* __restrict__ out)
{
    __shared__ __align__(16) unsigned char sm[40960];
    char* smp = reinterpret_cast<char*>(sm);
    const uint32_t sb = smem_u32(sm);

    const int tid = threadIdx.x, warp = tid >> 5, lane = tid & 31;
    const int rowBase = blockIdx.x * 128;
    const int colBase = blockIdx.y * 128;
    const int m0 = (warp & 1) * 64;
    const int n0 = (warp >> 1) * 32;
    const int nch = (rowBase < N_NODES) ? 24 : 8;

    const uint32_t aBase = sb + (uint32_t)(m0 + (lane & 15)) * 80u + ((lane >> 4) << 4);
    const uint32_t bBase = sb + 20480u + (uint32_t)(n0 + (lane & 7)) * 80u + (((lane >> 3) & 1) << 4);

    float acc[4][4][4];
    #pragma unroll
    for (int mb = 0; mb < 4; mb++)
        #pragma unroll
        for (int nb = 0; nb < 4; nb++)
            #pragma unroll
            for (int e = 0; e < 4; e++) acc[mb][nb][e] = 0.f;

    const int r = tid >> 1, seg = tid & 1;        // 128 rows x 2 segs of 16B per iter

    for (int ch = 0; ch < nch; ch++) {
        // ---- A copy: 128 rows x 64B, h and l ----
        {
            const unsigned short *Ah_src, *Al_src;
            int strideA;
            if (ch < 8) { Ah_src = g_xh + (size_t)rowBase * 256 + ch * 32;
                          Al_src = g_xl + (size_t)rowBase * 256 + ch * 32; strideA = 256; }
            else        { Ah_src = g_ph + (size_t)rowBase * 512 + (ch - 8) * 32;
                          Al_src = g_pl + (size_t)rowBase * 512 + (ch - 8) * 32; strideA = 512; }
            #pragma unroll
            for (int half = 0; half < 2; half++) {
                size_t go = (size_t)r * strideA + (half * 2 + seg) * 8;
                int so = r * 80 + (half * 2 + seg) * 16;
                *reinterpret_cast<uint4*>(smp + so)         = *reinterpret_cast<const uint4*>(Ah_src + go);
                *reinterpret_cast<uint4*>(smp + 10240 + so) = *reinterpret_cast<const uint4*>(Al_src + go);
            }
        }
        // ---- B copy: 128 rows x 64B, h and l ----
        {
            const unsigned short *Bh_src, *Bl_src;
            int Kb, kk;
            if (ch < 8) { Bh_src = g_B0h; Bl_src = g_B0l; Kb = 256; kk = ch * 32; }
            else        { Bh_src = g_B1h; Bl_src = g_B1l; Kb = 512; kk = (ch - 8) * 32; }
            #pragma unroll
            for (int half = 0; half < 2; half++) {
                size_t go = (size_t)(colBase + r) * Kb + kk + (half * 2 + seg) * 8;
                int so = r * 80 + (half * 2 + seg) * 16;
                *reinterpret_cast<uint4*>(smp + 20480 + so) = *reinterpret_cast<const uint4*>(Bh_src + go);
                *reinterpret_cast<uint4*>(smp + 30720 + so) = *reinterpret_cast<const uint4*>(Bl_src + go);
            }
        }
        __syncthreads();

        #pragma unroll
        for (int ks = 0; ks < 32; ks += 16) {
            unsigned bh[4][2], bl[4][2];
            #pragma unroll
            for (int nb = 0; nb < 4; nb++) {
                uint32_t b = bBase + nb * (8 * 80) + ks * 2;
                LDM_X2(bh[nb][0], bh[nb][1], b);
                LDM_X2(bl[nb][0], bl[nb][1], b + 10240u);
            }
            #pragma unroll
            for (int mb = 0; mb < 4; mb++) {
                unsigned ah[4], al[4];
                uint32_t a = aBase + mb * (16 * 80) + ks * 2;
                LDM_X4(ah[0], ah[1], ah[2], ah[3], a);
                LDM_X4(al[0], al[1], al[2], al[3], a + 10240u);
                #pragma unroll
                for (int nb = 0; nb < 4; nb++) {
                    MMA_BF16(acc[mb][nb], ah, bh[nb]);
                    MMA_BF16(acc[mb][nb], ah, bl[nb]);
                    MMA_BF16(acc[mb][nb], al, bh[nb]);
                }
            }
        }
        __syncthreads();
    }

    // ---- epilogue ----
    const int g = lane >> 2, t4 = lane & 3;
    #pragma unroll
    for (int mb = 0; mb < 4; mb++) {
        int r0 = rowBase + m0 + mb * 16 + g;
        #pragma unroll
        for (int nb = 0; nb < 4; nb++) {
            int c = colBase + n0 + nb * 8 + 2 * t4;
            float b0 = g_bias[c], b1 = g_bias[c + 1];
            *reinterpret_cast<float2*>(&out[(size_t)r0 * C_OUT + c]) =
                make_float2(acc[mb][nb][0] + b0, acc[mb][nb][1] + b1);
            *reinterpret_cast<float2*>(&out[(size_t)(r0 + 8) * C_OUT + c]) =
                make_float2(acc[mb][nb][2] + b0, acc[mb][nb][3] + b1);
        }
    }
}

// ---------------- launcher ----------------
extern "C" void kernel_launch(void* const* d_in, const int* in_sizes, int n_in,
                              void* d_out, int out_size)
{
    const float* x    = (const float*)d_in[0];
    const float* adj1 = (const float*)d_in[1];
    const float* adj2 = (const float*)d_in[2];
    const float* W0a  = (const float*)d_in[3];
    const float* W1a  = (const float*)d_in[4];
    const float* bca  = (const float*)d_in[5];
    const float* W0b  = (const float*)d_in[6];
    const float* W1b  = (const float*)d_in[7];
    const float* bcb  = (const float*)d_in[8];
    const float* Wp   = (const float*)d_in[9];
    const float* bp   = (const float*)d_in[10];
    float* out = (float*)d_out;

    // L1: row_scan + weight folding(+bf16 split) + bias + x pre-split
    mega1<<<8241 + 8192, 256>>>(x, adj1, adj2, W0a, W1a, W0b, W1b, Wp, bca, bcb, bp);
    // L2: sparse propagation (emits bf16 h/l directly)
    prop_kernel<<<dim3(N_NODES, 2), 256>>>(x);
    // L3: fused bf16 tensor-core GEMM
    gemm_mma<<<dim3(M_TOTAL / 128, C_OUT / 128), 256>>>(out);
}

// round 8
// speedup vs baseline: 1.8637x; 1.0657x over previous
#include <cuda_runtime.h>
#include <cuda_bf16.h>
#include <cstdint>

#define N_NODES 4096
#define C_IN    256
#define C_OUT   256
#define BATCH   8
#define M_TOTAL (BATCH * N_NODES)
#define CAP     256

// ---------------- device scratch ----------------
__device__ float g_dis[2][N_NODES];
__device__ int   g_nnz[2][N_NODES];
__device__ __align__(16) int   g_cj[2][N_NODES][CAP];
__device__ __align__(16) float g_cv[2][N_NODES][CAP];
__device__ float g_bias[C_OUT];
// bf16 h/l splits, A-side ([M][K] row-major) and B-side ([N][K])
__device__ __align__(16) unsigned short g_xh[M_TOTAL * C_IN],  g_xl[M_TOTAL * C_IN];
__device__ __align__(16) unsigned short g_ph[N_NODES * 512],   g_pl[N_NODES * 512];
__device__ __align__(16) unsigned short g_B0h[C_OUT * C_IN],      g_B0l[C_OUT * C_IN];
__device__ __align__(16) unsigned short g_B1h[C_OUT * 2 * C_OUT], g_B1l[C_OUT * 2 * C_OUT];

__device__ __forceinline__ uint32_t smem_u32(const void* p) {
    uint32_t a;
    asm("{ .reg .u64 t; cvta.to.shared.u64 t, %1; cvt.u32.u64 %0, t; }" : "=r"(a) : "l"(p));
    return a;
}

// =================== L1 mega kernel ===================
// blocks [0,8192): row_scan;  [8192,8240): fold (48);  8240: bias;
// [8241, 8241+8192): x pre-split.

struct ScanSh { int cnt; float sdeg[8]; };
struct FoldSh { float As[16][64]; float Bs[16][64]; };

__device__ void row_scan_body(char* sh, const float* __restrict__ adj, int i, int a)
{
    ScanSh* s = reinterpret_cast<ScanSh*>(sh);
    const int t = threadIdx.x, lane = t & 31, warp = t >> 5;
    if (t == 0) s->cnt = 0;
    __syncthreads();

    // front-batched loads: MLP = 4
    const float4* r4 = reinterpret_cast<const float4*>(adj + (size_t)i * N_NODES);
    float4 v[4];
    #pragma unroll
    for (int ss = 0; ss < 4; ss++) v[ss] = r4[t + 256 * ss];

    float deg = 0.f;
    const unsigned lmask = (1u << lane) - 1u;
    #pragma unroll
    for (int ss = 0; ss < 4; ss++) {
        float vv[4] = {v[ss].x, v[ss].y, v[ss].z, v[ss].w};
        int jb = (t + 256 * ss) * 4;
        #pragma unroll
        for (int e = 0; e < 4; e++) {
            int j = jb + e;
            float val = vv[e];
            bool pred = (j != i) && (val != 0.f);
            if (pred) deg += val;
            unsigned mask = __ballot_sync(0xffffffffu, pred);
            if (mask) {
                int base = 0;
                if (lane == 0) base = atomicAdd(&s->cnt, __popc(mask));
                base = __shfl_sync(0xffffffffu, base, 0);
                if (pred) {
                    int p = base + __popc(mask & lmask);
                    if (p < CAP) { g_cj[a][i][p] = j; g_cv[a][i][p] = val; }
                }
            }
        }
    }
    // warp-shuffle reduction of deg
    #pragma unroll
    for (int off = 16; off > 0; off >>= 1)
        deg += __shfl_xor_sync(0xffffffffu, deg, off);
    if (lane == 0) s->sdeg[warp] = deg;
    __syncthreads();
    if (t == 0) {
        float d = 0.f;
        #pragma unroll
        for (int w = 0; w < 8; w++) d += s->sdeg[w];
        g_dis[a][i] = (d > 0.f) ? rsqrtf(d) : 0.f;
        g_nnz[a][i] = min(s->cnt, CAP);
    }
}

__device__ void fold_body(char* sh, int fid,
                          const float* __restrict__ W0a, const float* __restrict__ W1a,
                          const float* __restrict__ W0b, const float* __restrict__ W1b,
                          const float* __restrict__ Wp)
{
    FoldSh* s = reinterpret_cast<FoldSh*>(sh);
    const int bx = fid & 3, by = (fid >> 2) & 3, job = fid >> 4;
    const float *A1, *B1, *A2 = nullptr, *B2 = nullptr;
    if (job == 0)      { A1 = W0a; B1 = Wp;         A2 = W0b; B2 = Wp + 65536; }
    else if (job == 1) { A1 = W1a; B1 = Wp; }
    else               { A1 = W1b; B1 = Wp + 65536; }

    const int tid = threadIdx.x;
    const int rowBase = bx * 64, colBase = by * 64;
    const int tx = tid & 15, ty = tid >> 4;

    float acc[4][4];
    #pragma unroll
    for (int i = 0; i < 4; i++)
        #pragma unroll
        for (int j = 0; j < 4; j++) acc[i][j] = 0.f;

    for (int pass = 0; pass < 2; pass++) {
        const float* A = pass ? A2 : A1;
        const float* B = pass ? B2 : B1;
        if (!A) break;
        for (int k0 = 0; k0 < 256; k0 += 16) {
            {
                int ar = tid >> 2, ac = (tid & 3) << 2;
                float4 av = *reinterpret_cast<const float4*>(&A[(size_t)(rowBase + ar) * 256 + k0 + ac]);
                s->As[ac + 0][ar] = av.x; s->As[ac + 1][ar] = av.y;
                s->As[ac + 2][ar] = av.z; s->As[ac + 3][ar] = av.w;
            }
            {
                int br = tid >> 4, bc = (tid & 15) << 2;
                *reinterpret_cast<float4*>(&s->Bs[br][bc]) =
                    *reinterpret_cast<const float4*>(&B[(size_t)(k0 + br) * 256 + colBase + bc]);
            }
            __syncthreads();
            #pragma unroll
            for (int k = 0; k < 16; k++) {
                float ra[4], rb[4];
                #pragma unroll
                for (int i = 0; i < 4; i++) ra[i] = s->As[k][ty * 4 + i];
                #pragma unroll
                for (int j = 0; j < 4; j++) rb[j] = s->Bs[k][tx * 4 + j];
                #pragma unroll
                for (int i = 0; i < 4; i++)
                    #pragma unroll
                    for (int j = 0; j < 4; j++) acc[i][j] += ra[i] * rb[j];
            }
            __syncthreads();
        }
    }
    #pragma unroll
    for (int i = 0; i < 4; i++) {
        int kIdx = rowBase + ty * 4 + i;
        #pragma unroll
        for (int j = 0; j < 4; j++) {
            int nIdx = colBase + tx * 4 + j;
            float v = acc[i][j];
            __nv_bfloat16 h = __float2bfloat16_rn(v);
            __nv_bfloat16 l = __float2bfloat16_rn(v - __bfloat162float(h));
            unsigned short hu = __bfloat16_as_ushort(h), lu = __bfloat16_as_ushort(l);
            if (job == 0)      { g_B0h[nIdx * 256 + kIdx] = hu; g_B0l[nIdx * 256 + kIdx] = lu; }
            else if (job == 1) { g_B1h[nIdx * 512 + kIdx] = hu; g_B1l[nIdx * 512 + kIdx] = lu; }
            else               { g_B1h[nIdx * 512 + 256 + kIdx] = hu; g_B1l[nIdx * 512 + 256 + kIdx] = lu; }
        }
    }
}

__device__ void bias_body(const float* __restrict__ bca, const float* __restrict__ bcb,
                          const float* __restrict__ bp,  const float* __restrict__ Wp)
{
    const int o = threadIdx.x;
    float acc = bp[o];
    #pragma unroll 8
    for (int k = 0; k < 256; k++)
        acc += bca[k] * Wp[k * 256 + o] + bcb[k] * Wp[(256 + k) * 256 + o];
    g_bias[o] = acc;
}

__device__ void xsplit_body(const float* __restrict__ x, int bid)
{
    int idx = bid * 1024 + threadIdx.x * 4;
    float4 v = *reinterpret_cast<const float4*>(x + idx);
    __nv_bfloat162 h01 = __floats2bfloat162_rn(v.x, v.y);
    __nv_bfloat162 h23 = __floats2bfloat162_rn(v.z, v.w);
    float2 f01 = __bfloat1622float2(h01);
    float2 f23 = __bfloat1622float2(h23);
    __nv_bfloat162 l01 = __floats2bfloat162_rn(v.x - f01.x, v.y - f01.y);
    __nv_bfloat162 l23 = __floats2bfloat162_rn(v.z - f23.x, v.w - f23.y);
    *reinterpret_cast<uint2*>(&g_xh[idx]) =
        make_uint2(*reinterpret_cast<unsigned*>(&h01), *reinterpret_cast<unsigned*>(&h23));
    *reinterpret_cast<uint2*>(&g_xl[idx]) =
        make_uint2(*reinterpret_cast<unsigned*>(&l01), *reinterpret_cast<unsigned*>(&l23));
}

__global__ void __launch_bounds__(256) mega1(const float* __restrict__ x,
                                             const float* __restrict__ adj1,
                                             const float* __restrict__ adj2,
                                             const float* __restrict__ W0a,
                                             const float* __restrict__ W1a,
                                             const float* __restrict__ W0b,
                                             const float* __restrict__ W1b,
                                             const float* __restrict__ Wp,
                                             const float* __restrict__ bca,
                                             const float* __restrict__ bcb,
                                             const float* __restrict__ bp)
{
    __shared__ __align__(16) char sh[sizeof(FoldSh)];
    const int id = blockIdx.x;
    if (id < 8192) {
        row_scan_body(sh, (id < 4096) ? adj1 : adj2, id & 4095, id >> 12);
    } else if (id < 8240) {
        fold_body(sh, id - 8192, W0a, W1a, W0b, W1b, Wp);
    } else if (id == 8240) {
        bias_body(bca, bcb, bp, Wp);
    } else {
        xsplit_body(x, id - 8241);
    }
}

// =================== L2: sparse propagation =======================
__global__ void __launch_bounds__(256) prop_kernel(const float* __restrict__ x)
{
    const int i = blockIdx.x, a = blockIdx.y, t = threadIdx.x;
    __shared__ int   sj[CAP];
    __shared__ float sv[CAP];
    const int nnz = g_nnz[a][i];
    for (int e = t; e < nnz; e += 256) {
        int j = g_cj[a][i][e];
        sj[e] = j;
        sv[e] = g_cv[a][i][e] * g_dis[a][j];
    }
    __syncthreads();
    float acc = 0.f;
    for (int e = 0; e < nnz; e++)
        acc += sv[e] * x[(size_t)sj[e] * C_IN + t];
    float val = -g_dis[a][i] * acc;
    __nv_bfloat16 h = __float2bfloat16_rn(val);
    __nv_bfloat16 l = __float2bfloat16_rn(val - __bfloat162float(h));
    size_t off = (size_t)i * 512 + a * 256 + t;
    g_ph[off] = __bfloat16_as_ushort(h);
    g_pl[off] = __bfloat16_as_ushort(l);
}

// =================== L3: fused bf16 mma.sync GEMM, cp.async pipelined ====
// out[m][n] = bias[n] + x[m]@Weff0[:,n] (+ prop[m]@Weff1[:,n] for m<4096)
// D = Ah*Bh + Ah*Bl + Al*Bh ; CTA 128x128, BK=32, warps 2(M)x4(N).
// Dynamic smem: 2 stages x 40960B; per stage: Ah@0 Al@10240 Bh@20480 Bl@30720.

#define LDM_X4(r0, r1, r2, r3, a) \
    asm volatile("ldmatrix.sync.aligned.m8n8.x4.shared.b16 {%0,%1,%2,%3}, [%4];" \
                 : "=r"(r0), "=r"(r1), "=r"(r2), "=r"(r3) : "r"(a))
#define LDM_X2(r0, r1, a) \
    asm volatile("ldmatrix.sync.aligned.m8n8.x2.shared.b16 {%0,%1}, [%2];" \
                 : "=r"(r0), "=r"(r1) : "r"(a))
#define MMA_BF16(d, a, b) \
    asm volatile("mma.sync.aligned.m16n8k16.row.col.f32.bf16.bf16.f32 " \
                 "{%0,%1,%2,%3}, {%4,%5,%6,%7}, {%8,%9}, {%0,%1,%2,%3};" \
                 : "+f"((d)[0]), "+f"((d)[1]), "+f"((d)[2]), "+f"((d)[3]) \
                 : "r"((a)[0]), "r"((a)[1]), "r"((a)[2]), "r"((a)[3]),   \
                   "r"((b)[0]), "r"((b)[1]))
#define CP16(sa, gp) \
    asm volatile("cp.async.cg.shared.global [%0], [%1], 16;" :: "r"(sa), "l"(gp))
#define CP_COMMIT() asm volatile("cp.async.commit_group;" ::: "memory")
#define CP_WAIT0()  asm volatile("cp.async.wait_group 0;" ::: "memory")
#define CP_WAIT1()  asm volatile("cp.async.wait_group 1;" ::: "memory")

static constexpr int GSTAGE = 40960;
static constexpr int GSM_TOTAL = 2 * GSTAGE;

__device__ __forceinline__ void issue_chunk(uint32_t st, int r, int seg,
                                            int rowBase, int colBase, int ch)
{
    const unsigned short *Ah_src, *Al_src;
    int strideA;
    if (ch < 8) { Ah_src = g_xh + (size_t)rowBase * 256 + ch * 32;
                  Al_src = g_xl + (size_t)rowBase * 256 + ch * 32; strideA = 256; }
    else        { Ah_src = g_ph + (size_t)rowBase * 512 + (ch - 8) * 32;
                  Al_src = g_pl + (size_t)rowBase * 512 + (ch - 8) * 32; strideA = 512; }
    #pragma unroll
    for (int half = 0; half < 2; half++) {
        size_t go = (size_t)r * strideA + (half * 2 + seg) * 8;
        uint32_t so = r * 80 + (half * 2 + seg) * 16;
        CP16(st + so,         Ah_src + go);
        CP16(st + 10240 + so, Al_src + go);
    }
    const unsigned short *Bh_src, *Bl_src;
    int Kb, kk;
    if (ch < 8) { Bh_src = g_B0h; Bl_src = g_B0l; Kb = 256; kk = ch * 32; }
    else        { Bh_src = g_B1h; Bl_src = g_B1l; Kb = 512; kk = (ch - 8) * 32; }
    #pragma unroll
    for (int half = 0; half < 2; half++) {
        size_t go = (size_t)(colBase + r) * Kb + kk + (half * 2 + seg) * 8;
        uint32_t so = r * 80 + (half * 2 + seg) * 16;
        CP16(st + 20480 + so, Bh_src + go);
        CP16(st + 30720 + so, Bl_src + go);
    }
}

__global__ void __launch_bounds__(256, 2) gemm_mma(float* __restrict__ out)
{
    extern __shared__ __align__(16) unsigned char smd[];
    const uint32_t sb = smem_u32(smd);

    const int tid = threadIdx.x, warp = tid >> 5, lane = tid & 31;
    const int rowBase = blockIdx.x * 128;
    const int colBase = blockIdx.y * 128;
    const int m0 = (warp & 1) * 64;
    const int n0 = (warp >> 1) * 32;
    const int nch = (rowBase < N_NODES) ? 24 : 8;

    const uint32_t aOff = (uint32_t)(m0 + (lane & 15)) * 80u + ((lane >> 4) << 4);
    const uint32_t bOff = 20480u + (uint32_t)(n0 + (lane & 7)) * 80u + (((lane >> 3) & 1) << 4);

    float acc[4][4][4];
    #pragma unroll
    for (int mb = 0; mb < 4; mb++)
        #pragma unroll
        for (int nb = 0; nb < 4; nb++)
            #pragma unroll
            for (int e = 0; e < 4; e++) acc[mb][nb][e] = 0.f;

    const int r = tid >> 1, seg = tid & 1;

    issue_chunk(sb, r, seg, rowBase, colBase, 0);
    CP_COMMIT();

    for (int ch = 0; ch < nch; ch++) {
        const int cur = ch & 1;
        if (ch + 1 < nch) {
            issue_chunk(sb + ((ch + 1) & 1) * GSTAGE, r, seg, rowBase, colBase, ch + 1);
            CP_COMMIT();
            CP_WAIT1();
        } else {
            CP_WAIT0();
        }
        __syncthreads();

        const uint32_t aB = sb + cur * GSTAGE + aOff;
        const uint32_t bB = sb + cur * GSTAGE + bOff;
        #pragma unroll
        for (int ks = 0; ks < 32; ks += 16) {
            unsigned bh[4][2], bl[4][2];
            #pragma unroll
            for (int nb = 0; nb < 4; nb++) {
                uint32_t b = bB + nb * (8 * 80) + ks * 2;
                LDM_X2(bh[nb][0], bh[nb][1], b);
                LDM_X2(bl[nb][0], bl[nb][1], b + 10240u);
            }
            #pragma unroll
            for (int mb = 0; mb < 4; mb++) {
                unsigned ah[4], al[4];
                uint32_t a = aB + mb * (16 * 80) + ks * 2;
                LDM_X4(ah[0], ah[1], ah[2], ah[3], a);
                LDM_X4(al[0], al[1], al[2], al[3], a + 10240u);
                #pragma unroll
                for (int nb = 0; nb < 4; nb++) {
                    MMA_BF16(acc[mb][nb], ah, bh[nb]);
                    MMA_BF16(acc[mb][nb], ah, bl[nb]);
                    MMA_BF16(acc[mb][nb], al, bh[nb]);
                }
            }
        }
        __syncthreads();
    }

    // ---- epilogue ----
    const int g = lane >> 2, t4 = lane & 3;
    #pragma unroll
    for (int mb = 0; mb < 4; mb++) {
        int r0 = rowBase + m0 + mb * 16 + g;
        #pragma unroll
        for (int nb = 0; nb < 4; nb++) {
            int c = colBase + n0 + nb * 8 + 2 * t4;
            float b0 = g_bias[c], b1 = g_bias[c + 1];
            *reinterpret_cast<float2*>(&out[(size_t)r0 * C_OUT + c]) =
                make_float2(acc[mb][nb][0] + b0, acc[mb][nb][1] + b1);
            *reinterpret_cast<float2*>(&out[(size_t)(r0 + 8) * C_OUT + c]) =
                make_float2(acc[mb][nb][2] + b0, acc[mb][nb][3] + b1);
        }
    }
}

// ---------------- launcher ----------------
extern "C" void kernel_launch(void* const* d_in, const int* in_sizes, int n_in,
                              void* d_out, int out_size)
{
    const float* x    = (const float*)d_in[0];
    const float* adj1 = (const float*)d_in[1];
    const float* adj2 = (const float*)d_in[2];
    const float* W0a  = (const float*)d_in[3];
    const float* W1a  = (const float*)d_in[4];
    const float* bca  = (const float*)d_in[5];
    const float* W0b  = (const float*)d_in[6];
    const float* W1b  = (const float*)d_in[7];
    const float* bcb  = (const float*)d_in[8];
    const float* Wp   = (const float*)d_in[9];
    const float* bp   = (const float*)d_in[10];
    float* out = (float*)d_out;

    cudaFuncSetAttribute(gemm_mma, cudaFuncAttributeMaxDynamicSharedMemorySize, GSM_TOTAL);

    // L1: row_scan + weight folding(+bf16 split) + bias + x pre-split
    mega1<<<8241 + 8192, 256>>>(x, adj1, adj2, W0a, W1a, W0b, W1b, Wp, bca, bcb, bp);
    // L2: sparse propagation (emits bf16 h/l directly)
    prop_kernel<<<dim3(N_NODES, 2), 256>>>(x);
    // L3: fused bf16 tensor-core GEMM, double-buffered cp.async
    gemm_mma<<<dim3(M_TOTAL / 128, C_OUT / 128), 256, GSM_TOTAL>>>(out);
}

// round 15
// speedup vs baseline: 1.8928x; 1.0156x over previous
#include <cuda_runtime.h>
#include <cuda_bf16.h>
#include <cstdint>

#define N_NODES 4096
#define C_IN    256
#define C_OUT   256
#define BATCH   8
#define M_TOTAL (BATCH * N_NODES)
#define CAP     256

// ---------------- device scratch ----------------
__device__ float g_dis[2][N_NODES];
__device__ int   g_nnz[2][N_NODES];
__device__ __align__(16) int   g_cj[2][N_NODES][CAP];
__device__ __align__(16) float g_cv[2][N_NODES][CAP];
__device__ float g_bias[C_OUT];
__device__ __align__(16) unsigned short g_xh[M_TOTAL * C_IN],  g_xl[M_TOTAL * C_IN];
__device__ __align__(16) unsigned short g_ph[N_NODES * 512],   g_pl[N_NODES * 512];
__device__ __align__(16) unsigned short g_B0h[C_OUT * C_IN],      g_B0l[C_OUT * C_IN];
__device__ __align__(16) unsigned short g_B1h[C_OUT * 2 * C_OUT], g_B1l[C_OUT * 2 * C_OUT];

__device__ __forceinline__ uint32_t smem_u32(const void* p) {
    uint32_t a;
    asm("{ .reg .u64 t; cvta.to.shared.u64 t, %1; cvt.u32.u64 %0, t; }" : "=r"(a) : "l"(p));
    return a;
}

// =================== L1 mega kernel ===================
// blocks [0,8192): row_scan;  [8192,8240): fold;  8240: bias; rest: x pre-split.

struct ScanSh { int woff[8]; float wdeg[8]; };
struct FoldSh { float As[16][64]; float Bs[16][64]; };

__device__ void row_scan_body(char* sh, const float* __restrict__ adj, int i, int a)
{
    ScanSh* s = reinterpret_cast<ScanSh*>(sh);
    const int t = threadIdx.x, lane = t & 31, warp = t >> 5;

    // front-batched loads: MLP = 4
    const float4* r4 = reinterpret_cast<const float4*>(adj + (size_t)i * N_NODES);
    float4 v[4];
    #pragma unroll
    for (int ss = 0; ss < 4; ss++) v[ss] = r4[t + 256 * ss];

    // phase 1: pure local count + deg (no sync, no collectives)
    int cnt = 0;
    float deg = 0.f;
    #pragma unroll
    for (int ss = 0; ss < 4; ss++) {
        float vv[4] = {v[ss].x, v[ss].y, v[ss].z, v[ss].w};
        int jb = (t + 256 * ss) * 4;
        #pragma unroll
        for (int e = 0; e < 4; e++) {
            if ((jb + e) != i && vv[e] != 0.f) { cnt++; deg += vv[e]; }
        }
    }

    // phase 2: warp inclusive scan of cnt, warp reduce of deg
    int inc = cnt;
    #pragma unroll
    for (int off = 1; off < 32; off <<= 1) {
        int n = __shfl_up_sync(0xffffffffu, inc, off);
        if (lane >= off) inc += n;
    }
    float dw = deg;
    #pragma unroll
    for (int off = 16; off > 0; off >>= 1)
        dw += __shfl_xor_sync(0xffffffffu, dw, off);
    if (lane == 31) s->woff[warp] = inc;   // warp total (temporarily)
    if (lane == 0)  s->wdeg[warp] = dw;
    __syncthreads();
    if (t == 0) {
        int run = 0; float ds = 0.f;
        #pragma unroll
        for (int w = 0; w < 8; w++) {
            int c = s->woff[w];
            s->woff[w] = run;              // exclusive warp base
            run += c;
            ds += s->wdeg[w];
        }
        g_dis[a][i] = (ds > 0.f) ? rsqrtf(ds) : 0.f;
        g_nnz[a][i] = min(run, CAP);
    }
    __syncthreads();

    // phase 3: independent writes to reserved ranges
    int p = s->woff[warp] + inc - cnt;
    #pragma unroll
    for (int ss = 0; ss < 4; ss++) {
        float vv[4] = {v[ss].x, v[ss].y, v[ss].z, v[ss].w};
        int jb = (t + 256 * ss) * 4;
        #pragma unroll
        for (int e = 0; e < 4; e++) {
            int j = jb + e;
            if (j != i && vv[e] != 0.f) {
                if (p < CAP) { g_cj[a][i][p] = j; g_cv[a][i][p] = vv[e]; }
                p++;
            }
        }
    }
}

__device__ void fold_body(char* sh, int fid,
                          const float* __restrict__ W0a, const float* __restrict__ W1a,
                          const float* __restrict__ W0b, const float* __restrict__ W1b,
                          const float* __restrict__ Wp)
{
    FoldSh* s = reinterpret_cast<FoldSh*>(sh);
    const int bx = fid & 3, by = (fid >> 2) & 3, job = fid >> 4;
    const float *A1, *B1, *A2 = nullptr, *B2 = nullptr;
    if (job == 0)      { A1 = W0a; B1 = Wp;         A2 = W0b; B2 = Wp + 65536; }
    else if (job == 1) { A1 = W1a; B1 = Wp; }
    else               { A1 = W1b; B1 = Wp + 65536; }

    const int tid = threadIdx.x;
    const int rowBase = bx * 64, colBase = by * 64;
    const int tx = tid & 15, ty = tid >> 4;

    float acc[4][4];
    #pragma unroll
    for (int i = 0; i < 4; i++)
        #pragma unroll
        for (int j = 0; j < 4; j++) acc[i][j] = 0.f;

    for (int pass = 0; pass < 2; pass++) {
        const float* A = pass ? A2 : A1;
        const float* B = pass ? B2 : B1;
        if (!A) break;
        for (int k0 = 0; k0 < 256; k0 += 16) {
            {
                int ar = tid >> 2, ac = (tid & 3) << 2;
                float4 av = *reinterpret_cast<const float4*>(&A[(size_t)(rowBase + ar) * 256 + k0 + ac]);
                s->As[ac + 0][ar] = av.x; s->As[ac + 1][ar] = av.y;
                s->As[ac + 2][ar] = av.z; s->As[ac + 3][ar] = av.w;
            }
            {
                int br = tid >> 4, bc = (tid & 15) << 2;
                *reinterpret_cast<float4*>(&s->Bs[br][bc]) =
                    *reinterpret_cast<const float4*>(&B[(size_t)(k0 + br) * 256 + colBase + bc]);
            }
            __syncthreads();
            #pragma unroll
            for (int k = 0; k < 16; k++) {
                float ra[4], rb[4];
                #pragma unroll
                for (int i = 0; i < 4; i++) ra[i] = s->As[k][ty * 4 + i];
                #pragma unroll
                for (int j = 0; j < 4; j++) rb[j] = s->Bs[k][tx * 4 + j];
                #pragma unroll
                for (int i = 0; i < 4; i++)
                    #pragma unroll
                    for (int j = 0; j < 4; j++) acc[i][j] += ra[i] * rb[j];
            }
            __syncthreads();
        }
    }
    #pragma unroll
    for (int i = 0; i < 4; i++) {
        int kIdx = rowBase + ty * 4 + i;
        #pragma unroll
        for (int j = 0; j < 4; j++) {
            int nIdx = colBase + tx * 4 + j;
            float v = acc[i][j];
            __nv_bfloat16 h = __float2bfloat16_rn(v);
            __nv_bfloat16 l = __float2bfloat16_rn(v - __bfloat162float(h));
            unsigned short hu = __bfloat16_as_ushort(h), lu = __bfloat16_as_ushort(l);
            if (job == 0)      { g_B0h[nIdx * 256 + kIdx] = hu; g_B0l[nIdx * 256 + kIdx] = lu; }
            else if (job == 1) { g_B1h[nIdx * 512 + kIdx] = hu; g_B1l[nIdx * 512 + kIdx] = lu; }
            else               { g_B1h[nIdx * 512 + 256 + kIdx] = hu; g_B1l[nIdx * 512 + 256 + kIdx] = lu; }
        }
    }
}

__device__ void bias_body(const float* __restrict__ bca, const float* __restrict__ bcb,
                          const float* __restrict__ bp,  const float* __restrict__ Wp)
{
    const int o = threadIdx.x;
    float acc = bp[o];
    #pragma unroll 8
    for (int k = 0; k < 256; k++)
        acc += bca[k] * Wp[k * 256 + o] + bcb[k] * Wp[(256 + k) * 256 + o];
    g_bias[o] = acc;
}

__device__ void xsplit_body(const float* __restrict__ x, int bid)
{
    int idx = bid * 1024 + threadIdx.x * 4;
    float4 v = *reinterpret_cast<const float4*>(x + idx);
    __nv_bfloat162 h01 = __floats2bfloat162_rn(v.x, v.y);
    __nv_bfloat162 h23 = __floats2bfloat162_rn(v.z, v.w);
    float2 f01 = __bfloat1622float2(h01);
    float2 f23 = __bfloat1622float2(h23);
    __nv_bfloat162 l01 = __floats2bfloat162_rn(v.x - f01.x, v.y - f01.y);
    __nv_bfloat162 l23 = __floats2bfloat162_rn(v.z - f23.x, v.w - f23.y);
    *reinterpret_cast<uint2*>(&g_xh[idx]) =
        make_uint2(*reinterpret_cast<unsigned*>(&h01), *reinterpret_cast<unsigned*>(&h23));
    *reinterpret_cast<uint2*>(&g_xl[idx]) =
        make_uint2(*reinterpret_cast<unsigned*>(&l01), *reinterpret_cast<unsigned*>(&l23));
}

__global__ void __launch_bounds__(256) mega1(const float* __restrict__ x,
                                             const float* __restrict__ adj1,
                                             const float* __restrict__ adj2,
                                             const float* __restrict__ W0a,
                                             const float* __restrict__ W1a,
                                             const float* __restrict__ W0b,
                                             const float* __restrict__ W1b,
                                             const float* __restrict__ Wp,
                                             const float* __restrict__ bca,
                                             const float* __restrict__ bcb,
                                             const float* __restrict__ bp)
{
    __shared__ __align__(16) char sh[sizeof(FoldSh)];
    const int id = blockIdx.x;
    if (id < 8192) {
        row_scan_body(sh, (id < 4096) ? adj1 : adj2, id & 4095, id >> 12);
    } else if (id < 8240) {
        fold_body(sh, id - 8192, W0a, W1a, W0b, W1b, Wp);
    } else if (id == 8240) {
        bias_body(bca, bcb, bp, Wp);
    } else {
        xsplit_body(x, id - 8241);
    }
}

// =================== L2: sparse propagation =======================
// 4 (row, adj) units per block; 64 threads/unit; float4 channels.
__global__ void __launch_bounds__(256) prop_kernel(const float* __restrict__ x)
{
    __shared__ int   sj[4][CAP];
    __shared__ float sv[4][CAP];
    const int tid = threadIdx.x;
    const int unit = tid >> 6;               // 0..3
    const int c = tid & 63;                  // channel quad
    const int uid = blockIdx.x * 4 + unit;   // 0..8191
    const int a = uid >> 12, i = uid & 4095;
    const int nnz = g_nnz[a][i];

    for (int e = c; e < nnz; e += 64) {
        int j = g_cj[a][i][e];
        sj[unit][e] = j;
        sv[unit][e] = g_cv[a][i][e] * g_dis[a][j];
    }
    __syncthreads();

    const float4* x4 = reinterpret_cast<const float4*>(x);
    float4 acc = make_float4(0.f, 0.f, 0.f, 0.f);
    for (int e = 0; e < nnz; e++) {
        float4 xv = x4[(size_t)sj[unit][e] * 64 + c];
        float s = sv[unit][e];
        acc.x += s * xv.x; acc.y += s * xv.y;
        acc.z += s * xv.z; acc.w += s * xv.w;
    }
    float d = -g_dis[a][i];
    float vv[4] = {d * acc.x, d * acc.y, d * acc.z, d * acc.w};
    unsigned short hs[4], ls[4];
    #pragma unroll
    for (int k = 0; k < 4; k++) {
        __nv_bfloat16 h = __float2bfloat16_rn(vv[k]);
        __nv_bfloat16 l = __float2bfloat16_rn(vv[k] - __bfloat162float(h));
        hs[k] = __bfloat16_as_ushort(h);
        ls[k] = __bfloat16_as_ushort(l);
    }
    size_t off = (size_t)i * 512 + a * 256 + c * 4;
    *reinterpret_cast<uint2*>(&g_ph[off]) = *reinterpret_cast<uint2*>(hs);
    *reinterpret_cast<uint2*>(&g_pl[off]) = *reinterpret_cast<uint2*>(ls);
}

// =================== L3: fused bf16 mma.sync GEMM, cp.async pipelined ====
#define LDM_X4(r0, r1, r2, r3, a) \
    asm volatile("ldmatrix.sync.aligned.m8n8.x4.shared.b16 {%0,%1,%2,%3}, [%4];" \
                 : "=r"(r0), "=r"(r1), "=r"(r2), "=r"(r3) : "r"(a))
#define LDM_X2(r0, r1, a) \
    asm volatile("ldmatrix.sync.aligned.m8n8.x2.shared.b16 {%0,%1}, [%2];" \
                 : "=r"(r0), "=r"(r1) : "r"(a))
#define MMA_BF16(d, a, b) \
    asm volatile("mma.sync.aligned.m16n8k16.row.col.f32.bf16.bf16.f32 " \
                 "{%0,%1,%2,%3}, {%4,%5,%6,%7}, {%8,%9}, {%0,%1,%2,%3};" \
                 : "+f"((d)[0]), "+f"((d)[1]), "+f"((d)[2]), "+f"((d)[3]) \
                 : "r"((a)[0]), "r"((a)[1]), "r"((a)[2]), "r"((a)[3]),   \
                   "r"((b)[0]), "r"((b)[1]))
#define CP16(sa, gp) \
    asm volatile("cp.async.cg.shared.global [%0], [%1], 16;" :: "r"(sa), "l"(gp))
#define CP_COMMIT() asm volatile("cp.async.commit_group;" ::: "memory")
#define CP_WAIT0()  asm volatile("cp.async.wait_group 0;" ::: "memory")
#define CP_WAIT1()  asm volatile("cp.async.wait_group 1;" ::: "memory")

static constexpr int GSTAGE = 40960;
static constexpr int GSM_TOTAL = 2 * GSTAGE;

__device__ __forceinline__ void issue_chunk(uint32_t st, int r, int seg,
                                            int rowBase, int colBase, int ch)
{
    const unsigned short *Ah_src, *Al_src;
    int strideA;
    if (ch < 8) { Ah_src = g_xh + (size_t)rowBase * 256 + ch * 32;
                  Al_src = g_xl + (size_t)rowBase * 256 + ch * 32; strideA = 256; }
    else        { Ah_src = g_ph + (size_t)rowBase * 512 + (ch - 8) * 32;
                  Al_src = g_pl + (size_t)rowBase * 512 + (ch - 8) * 32; strideA = 512; }
    #pragma unroll
    for (int half = 0; half < 2; half++) {
        size_t go = (size_t)r * strideA + (half * 2 + seg) * 8;
        uint32_t so = r * 80 + (half * 2 + seg) * 16;
        CP16(st + so,         Ah_src + go);
        CP16(st + 10240 + so, Al_src + go);
    }
    const unsigned short *Bh_src, *Bl_src;
    int Kb, kk;
    if (ch < 8) { Bh_src = g_B0h; Bl_src = g_B0l; Kb = 256; kk = ch * 32; }
    else        { Bh_src = g_B1h; Bl_src = g_B1l; Kb = 512; kk = (ch - 8) * 32; }
    #pragma unroll
    for (int half = 0; half < 2; half++) {
        size_t go = (size_t)(colBase + r) * Kb + kk + (half * 2 + seg) * 8;
        uint32_t so = r * 80 + (half * 2 + seg) * 16;
        CP16(st + 20480 + so, Bh_src + go);
        CP16(st + 30720 + so, Bl_src + go);
    }
}

__global__ void __launch_bounds__(256, 2) gemm_mma(float* __restrict__ out)
{
    extern __shared__ __align__(16) unsigned char smd[];
    const uint32_t sb = smem_u32(smd);

    const int tid = threadIdx.x, warp = tid >> 5, lane = tid & 31;
    const int rowBase = blockIdx.x * 128;
    const int colBase = blockIdx.y * 128;
    const int m0 = (warp & 1) * 64;
    const int n0 = (warp >> 1) * 32;
    const int nch = (rowBase < N_NODES) ? 24 : 8;

    const uint32_t aOff = (uint32_t)(m0 + (lane & 15)) * 80u + ((lane >> 4) << 4);
    const uint32_t bOff = 20480u + (uint32_t)(n0 + (lane & 7)) * 80u + (((lane >> 3) & 1) << 4);

    float acc[4][4][4];
    #pragma unroll
    for (int mb = 0; mb < 4; mb++)
        #pragma unroll
        for (int nb = 0; nb < 4; nb++)
            #pragma unroll
            for (int e = 0; e < 4; e++) acc[mb][nb][e] = 0.f;

    const int r = tid >> 1, seg = tid & 1;

    issue_chunk(sb, r, seg, rowBase, colBase, 0);
    CP_COMMIT();

    for (int ch = 0; ch < nch; ch++) {
        const int cur = ch & 1;
        if (ch + 1 < nch) {
            issue_chunk(sb + ((ch + 1) & 1) * GSTAGE, r, seg, rowBase, colBase, ch + 1);
            CP_COMMIT();
            CP_WAIT1();
        } else {
            CP_WAIT0();
        }
        __syncthreads();

        const uint32_t aB = sb + cur * GSTAGE + aOff;
        const uint32_t bB = sb + cur * GSTAGE + bOff;
        #pragma unroll
        for (int ks = 0; ks < 32; ks += 16) {
            unsigned bh[4][2], bl[4][2];
            #pragma unroll
            for (int nb = 0; nb < 4; nb++) {
                uint32_t b = bB + nb * (8 * 80) + ks * 2;
                LDM_X2(bh[nb][0], bh[nb][1], b);
                LDM_X2(bl[nb][0], bl[nb][1], b + 10240u);
            }
            #pragma unroll
            for (int mb = 0; mb < 4; mb++) {
                unsigned ah[4], al[4];
                uint32_t a = aB + mb * (16 * 80) + ks * 2;
                LDM_X4(ah[0], ah[1], ah[2], ah[3], a);
                LDM_X4(al[0], al[1], al[2], al[3], a + 10240u);
                #pragma unroll
                for (int nb = 0; nb < 4; nb++) {
                    MMA_BF16(acc[mb][nb], ah, bh[nb]);
                    MMA_BF16(acc[mb][nb], ah, bl[nb]);
                    MMA_BF16(acc[mb][nb], al, bh[nb]);
                }
            }
        }
        __syncthreads();
    }

    const int g = lane >> 2, t4 = lane & 3;
    #pragma unroll
    for (int mb = 0; mb < 4; mb++) {
        int r0 = rowBase + m0 + mb * 16 + g;
        #pragma unroll
        for (int nb = 0; nb < 4; nb++) {
            int c = colBase + n0 + nb * 8 + 2 * t4;
            float b0 = g_bias[c], b1 = g_bias[c + 1];
            *reinterpret_cast<float2*>(&out[(size_t)r0 * C_OUT + c]) =
                make_float2(acc[mb][nb][0] + b0, acc[mb][nb][1] + b1);
            *reinterpret_cast<float2*>(&out[(size_t)(r0 + 8) * C_OUT + c]) =
                make_float2(acc[mb][nb][2] + b0, acc[mb][nb][3] + b1);
        }
    }
}

// ---------------- launcher ----------------
extern "C" void kernel_launch(void* const* d_in, const int* in_sizes, int n_in,
                              void* d_out, int out_size)
{
    const float* x    = (const float*)d_in[0];
    const float* adj1 = (const float*)d_in[1];
    const float* adj2 = (const float*)d_in[2];
    const float* W0a  = (const float*)d_in[3];
    const float* W1a  = (const float*)d_in[4];
    const float* bca  = (const float*)d_in[5];
    const float* W0b  = (const float*)d_in[6];
    const float* W1b  = (const float*)d_in[7];
    const float* bcb  = (const float*)d_in[8];
    const float* Wp   = (const float*)d_in[9];
    const float* bp   = (const float*)d_in[10];
    float* out = (float*)d_out;

    cudaFuncSetAttribute(gemm_mma, cudaFuncAttributeMaxDynamicSharedMemorySize, GSM_TOTAL);

    // L1: row_scan(scan-compaction) + weight folding + bias + x pre-split
    mega1<<<8241 + 8192, 256>>>(x, adj1, adj2, W0a, W1a, W0b, W1b, Wp, bca, bcb, bp);
    // L2: sparse propagation (float4 channels, 4 units/block)
    prop_kernel<<<2048, 256>>>(x);
    // L3: fused bf16 tensor-core GEMM, double-buffered cp.async
    gemm_mma<<<dim3(M_TOTAL / 128, C_OUT / 128), 256, GSM_TOTAL>>>(out);
}

// round 17
// speedup vs baseline: 1.9614x; 1.0363x over previous
#include <cuda_runtime.h>
#include <cuda_bf16.h>
#include <cstdint>

#define N_NODES 4096
#define C_IN    256
#define C_OUT   256
#define BATCH   8
#define M_TOTAL (BATCH * N_NODES)
#define CAP     256

// ---------------- device scratch ----------------
__device__ float g_dis[2][N_NODES];
__device__ int   g_nnz[2][N_NODES];
__device__ __align__(16) int   g_cj[2][N_NODES][CAP];
__device__ __align__(16) float g_cv[2][N_NODES][CAP];
__device__ float g_bias[C_OUT];
__device__ __align__(16) unsigned short g_xh[M_TOTAL * C_IN],  g_xl[M_TOTAL * C_IN];
__device__ __align__(16) unsigned short g_ph[N_NODES * 512],   g_pl[N_NODES * 512];
__device__ __align__(16) unsigned short g_B0h[C_OUT * C_IN],      g_B0l[C_OUT * C_IN];
__device__ __align__(16) unsigned short g_B1h[C_OUT * 2 * C_OUT], g_B1l[C_OUT * 2 * C_OUT];

__device__ __forceinline__ uint32_t smem_u32(const void* p) {
    uint32_t a;
    asm("{ .reg .u64 t; cvta.to.shared.u64 t, %1; cvt.u32.u64 %0, t; }" : "=r"(a) : "l"(p));
    return a;
}

// =================== L1 mega kernel ===================
// blocks [0,8192): row_scan;  [8192,8240): fold;  8240: bias; rest: x pre-split.

struct ScanSh { int cnt; float sdeg[256]; };
struct FoldSh { float As[16][64]; float Bs[16][64]; };

// round-7 variant (measured 69us): per-element shared atomicAdd compaction.
__device__ void row_scan_body(char* sh, const float* __restrict__ adj, int i, int a)
{
    ScanSh* s = reinterpret_cast<ScanSh*>(sh);
    const int t = threadIdx.x;
    if (t == 0) s->cnt = 0;
    __syncthreads();

    float deg = 0.f;
    const float4* r4 = reinterpret_cast<const float4*>(adj + (size_t)i * N_NODES);
    #pragma unroll
    for (int ss = 0; ss < 4; ss++) {
        int i4 = t + 256 * ss;
        float4 v = r4[i4];
        float vv[4] = {v.x, v.y, v.z, v.w};
        int jb = i4 * 4;
        #pragma unroll
        for (int e = 0; e < 4; e++) {
            int j = jb + e;
            float val = vv[e];
            if (j != i && val != 0.f) {
                deg += val;
                int p = atomicAdd(&s->cnt, 1);
                if (p < CAP) { g_cj[a][i][p] = j; g_cv[a][i][p] = val; }
            }
        }
    }
    s->sdeg[t] = deg;
    __syncthreads();
    for (int st = 128; st > 0; st >>= 1) {
        if (t < st) s->sdeg[t] += s->sdeg[t + st];
        __syncthreads();
    }
    if (t == 0) {
        float d = s->sdeg[0];
        g_dis[a][i] = (d > 0.f) ? rsqrtf(d) : 0.f;
        g_nnz[a][i] = min(s->cnt, CAP);
    }
}

__device__ void fold_body(char* sh, int fid,
                          const float* __restrict__ W0a, const float* __restrict__ W1a,
                          const float* __restrict__ W0b, const float* __restrict__ W1b,
                          const float* __restrict__ Wp)
{
    FoldSh* s = reinterpret_cast<FoldSh*>(sh);
    const int bx = fid & 3, by = (fid >> 2) & 3, job = fid >> 4;
    const float *A1, *B1, *A2 = nullptr, *B2 = nullptr;
    if (job == 0)      { A1 = W0a; B1 = Wp;         A2 = W0b; B2 = Wp + 65536; }
    else if (job == 1) { A1 = W1a; B1 = Wp; }
    else               { A1 = W1b; B1 = Wp + 65536; }

    const int tid = threadIdx.x;
    const int rowBase = bx * 64, colBase = by * 64;
    const int tx = tid & 15, ty = tid >> 4;

    float acc[4][4];
    #pragma unroll
    for (int i = 0; i < 4; i++)
        #pragma unroll
        for (int j = 0; j < 4; j++) acc[i][j] = 0.f;

    for (int pass = 0; pass < 2; pass++) {
        const float* A = pass ? A2 : A1;
        const float* B = pass ? B2 : B1;
        if (!A) break;
        for (int k0 = 0; k0 < 256; k0 += 16) {
            {
                int ar = tid >> 2, ac = (tid & 3) << 2;
                float4 av = *reinterpret_cast<const float4*>(&A[(size_t)(rowBase + ar) * 256 + k0 + ac]);
                s->As[ac + 0][ar] = av.x; s->As[ac + 1][ar] = av.y;
                s->As[ac + 2][ar] = av.z; s->As[ac + 3][ar] = av.w;
            }
            {
                int br = tid >> 4, bc = (tid & 15) << 2;
                *reinterpret_cast<float4*>(&s->Bs[br][bc]) =
                    *reinterpret_cast<const float4*>(&B[(size_t)(k0 + br) * 256 + colBase + bc]);
            }
            __syncthreads();
            #pragma unroll
            for (int k = 0; k < 16; k++) {
                float ra[4], rb[4];
                #pragma unroll
                for (int i = 0; i < 4; i++) ra[i] = s->As[k][ty * 4 + i];
                #pragma unroll
                for (int j = 0; j < 4; j++) rb[j] = s->Bs[k][tx * 4 + j];
                #pragma unroll
                for (int i = 0; i < 4; i++)
                    #pragma unroll
                    for (int j = 0; j < 4; j++) acc[i][j] += ra[i] * rb[j];
            }
            __syncthreads();
        }
    }
    #pragma unroll
    for (int i = 0; i < 4; i++) {
        int kIdx = rowBase + ty * 4 + i;
        #pragma unroll
        for (int j = 0; j < 4; j++) {
            int nIdx = colBase + tx * 4 + j;
            float v = acc[i][j];
            __nv_bfloat16 h = __float2bfloat16_rn(v);
            __nv_bfloat16 l = __float2bfloat16_rn(v - __bfloat162float(h));
            unsigned short hu = __bfloat16_as_ushort(h), lu = __bfloat16_as_ushort(l);
            if (job == 0)      { g_B0h[nIdx * 256 + kIdx] = hu; g_B0l[nIdx * 256 + kIdx] = lu; }
            else if (job == 1) { g_B1h[nIdx * 512 + kIdx] = hu; g_B1l[nIdx * 512 + kIdx] = lu; }
            else               { g_B1h[nIdx * 512 + 256 + kIdx] = hu; g_B1l[nIdx * 512 + 256 + kIdx] = lu; }
        }
    }
}

__device__ void bias_body(const float* __restrict__ bca, const float* __restrict__ bcb,
                          const float* __restrict__ bp,  const float* __restrict__ Wp)
{
    const int o = threadIdx.x;
    float acc = bp[o];
    #pragma unroll 8
    for (int k = 0; k < 256; k++)
        acc += bca[k] * Wp[k * 256 + o] + bcb[k] * Wp[(256 + k) * 256 + o];
    g_bias[o] = acc;
}

__device__ void xsplit_body(const float* __restrict__ x, int bid)
{
    int idx = bid * 1024 + threadIdx.x * 4;
    float4 v = *reinterpret_cast<const float4*>(x + idx);
    __nv_bfloat162 h01 = __floats2bfloat162_rn(v.x, v.y);
    __nv_bfloat162 h23 = __floats2bfloat162_rn(v.z, v.w);
    float2 f01 = __bfloat1622float2(h01);
    float2 f23 = __bfloat1622float2(h23);
    __nv_bfloat162 l01 = __floats2bfloat162_rn(v.x - f01.x, v.y - f01.y);
    __nv_bfloat162 l23 = __floats2bfloat162_rn(v.z - f23.x, v.w - f23.y);
    *reinterpret_cast<uint2*>(&g_xh[idx]) =
        make_uint2(*reinterpret_cast<unsigned*>(&h01), *reinterpret_cast<unsigned*>(&h23));
    *reinterpret_cast<uint2*>(&g_xl[idx]) =
        make_uint2(*reinterpret_cast<unsigned*>(&l01), *reinterpret_cast<unsigned*>(&l23));
}

__global__ void __launch_bounds__(256) mega1(const float* __restrict__ x,
                                             const float* __restrict__ adj1,
                                             const float* __restrict__ adj2,
                                             const float* __restrict__ W0a,
                                             const float* __restrict__ W1a,
                                             const float* __restrict__ W0b,
                                             const float* __restrict__ W1b,
                                             const float* __restrict__ Wp,
                                             const float* __restrict__ bca,
                                             const float* __restrict__ bcb,
                                             const float* __restrict__ bp)
{
    __shared__ __align__(16) char sh[sizeof(FoldSh)];
    const int id = blockIdx.x;
    if (id < 8192) {
        row_scan_body(sh, (id < 4096) ? adj1 : adj2, id & 4095, id >> 12);
    } else if (id < 8240) {
        fold_body(sh, id - 8192, W0a, W1a, W0b, W1b, Wp);
    } else if (id == 8240) {
        bias_body(bca, bcb, bp, Wp);
    } else {
        xsplit_body(x, id - 8241);
    }
}

// =================== L2: sparse propagation =======================
// 4 (row, adj) units per block; 64 threads/unit; float4 channels.
__global__ void __launch_bounds__(256) prop_kernel(const float* __restrict__ x)
{
    __shared__ int   sj[4][CAP];
    __shared__ float sv[4][CAP];
    const int tid = threadIdx.x;
    const int unit = tid >> 6;               // 0..3
    const int c = tid & 63;                  // channel quad
    const int uid = blockIdx.x * 4 + unit;   // 0..8191
    const int a = uid >> 12, i = uid & 4095;
    const int nnz = g_nnz[a][i];

    for (int e = c; e < nnz; e += 64) {
        int j = g_cj[a][i][e];
        sj[unit][e] = j;
        sv[unit][e] = g_cv[a][i][e] * g_dis[a][j];
    }
    __syncthreads();

    const float4* x4 = reinterpret_cast<const float4*>(x);
    float4 acc = make_float4(0.f, 0.f, 0.f, 0.f);
    for (int e = 0; e < nnz; e++) {
        float4 xv = x4[(size_t)sj[unit][e] * 64 + c];
        float s = sv[unit][e];
        acc.x += s * xv.x; acc.y += s * xv.y;
        acc.z += s * xv.z; acc.w += s * xv.w;
    }
    float d = -g_dis[a][i];
    float vv[4] = {d * acc.x, d * acc.y, d * acc.z, d * acc.w};
    unsigned short hs[4], ls[4];
    #pragma unroll
    for (int k = 0; k < 4; k++) {
        __nv_bfloat16 h = __float2bfloat16_rn(vv[k]);
        __nv_bfloat16 l = __float2bfloat16_rn(vv[k] - __bfloat162float(h));
        hs[k] = __bfloat16_as_ushort(h);
        ls[k] = __bfloat16_as_ushort(l);
    }
    size_t off = (size_t)i * 512 + a * 256 + c * 4;
    *reinterpret_cast<uint2*>(&g_ph[off]) = *reinterpret_cast<uint2*>(hs);
    *reinterpret_cast<uint2*>(&g_pl[off]) = *reinterpret_cast<uint2*>(ls);
}

// =================== L3: fused bf16 mma.sync GEMM, cp.async pipelined ====
#define LDM_X4(r0, r1, r2, r3, a) \
    asm volatile("ldmatrix.sync.aligned.m8n8.x4.shared.b16 {%0,%1,%2,%3}, [%4];" \
                 : "=r"(r0), "=r"(r1), "=r"(r2), "=r"(r3) : "r"(a))
#define LDM_X2(r0, r1, a) \
    asm volatile("ldmatrix.sync.aligned.m8n8.x2.shared.b16 {%0,%1}, [%2];" \
                 : "=r"(r0), "=r"(r1) : "r"(a))
#define MMA_BF16(d, a, b) \
    asm volatile("mma.sync.aligned.m16n8k16.row.col.f32.bf16.bf16.f32 " \
                 "{%0,%1,%2,%3}, {%4,%5,%6,%7}, {%8,%9}, {%0,%1,%2,%3};" \
                 : "+f"((d)[0]), "+f"((d)[1]), "+f"((d)[2]), "+f"((d)[3]) \
                 : "r"((a)[0]), "r"((a)[1]), "r"((a)[2]), "r"((a)[3]),   \
                   "r"((b)[0]), "r"((b)[1]))
#define CP16(sa, gp) \
    asm volatile("cp.async.cg.shared.global [%0], [%1], 16;" :: "r"(sa), "l"(gp))
#define CP_COMMIT() asm volatile("cp.async.commit_group;" ::: "memory")
#define CP_WAIT0()  asm volatile("cp.async.wait_group 0;" ::: "memory")
#define CP_WAIT1()  asm volatile("cp.async.wait_group 1;" ::: "memory")

static constexpr int GSTAGE = 40960;
static constexpr int GSM_TOTAL = 2 * GSTAGE;

__device__ __forceinline__ void issue_chunk(uint32_t st, int r, int seg,
                                            int rowBase, int colBase, int ch)
{
    const unsigned short *Ah_src, *Al_src;
    int strideA;
    if (ch < 8) { Ah_src = g_xh + (size_t)rowBase * 256 + ch * 32;
                  Al_src = g_xl + (size_t)rowBase * 256 + ch * 32; strideA = 256; }
    else        { Ah_src = g_ph + (size_t)rowBase * 512 + (ch - 8) * 32;
                  Al_src = g_pl + (size_t)rowBase * 512 + (ch - 8) * 32; strideA = 512; }
    #pragma unroll
    for (int half = 0; half < 2; half++) {
        size_t go = (size_t)r * strideA + (half * 2 + seg) * 8;
        uint32_t so = r * 80 + (half * 2 + seg) * 16;
        CP16(st + so,         Ah_src + go);
        CP16(st + 10240 + so, Al_src + go);
    }
    const unsigned short *Bh_src, *Bl_src;
    int Kb, kk;
    if (ch < 8) { Bh_src = g_B0h; Bl_src = g_B0l; Kb = 256; kk = ch * 32; }
    else        { Bh_src = g_B1h; Bl_src = g_B1l; Kb = 512; kk = (ch - 8) * 32; }
    #pragma unroll
    for (int half = 0; half < 2; half++) {
        size_t go = (size_t)(colBase + r) * Kb + kk + (half * 2 + seg) * 8;
        uint32_t so = r * 80 + (half * 2 + seg) * 16;
        CP16(st + 20480 + so, Bh_src + go);
        CP16(st + 30720 + so, Bl_src + go);
    }
}

__global__ void __launch_bounds__(256, 2) gemm_mma(float* __restrict__ out)
{
    extern __shared__ __align__(16) unsigned char smd[];
    const uint32_t sb = smem_u32(smd);

    const int tid = threadIdx.x, warp = tid >> 5, lane = tid & 31;
    const int rowBase = blockIdx.x * 128;
    const int colBase = blockIdx.y * 128;
    const int m0 = (warp & 1) * 64;
    const int n0 = (warp >> 1) * 32;
    const int nch = (rowBase < N_NODES) ? 24 : 8;

    const uint32_t aOff = (uint32_t)(m0 + (lane & 15)) * 80u + ((lane >> 4) << 4);
    const uint32_t bOff = 20480u + (uint32_t)(n0 + (lane & 7)) * 80u + (((lane >> 3) & 1) << 4);

    float acc[4][4][4];
    #pragma unroll
    for (int mb = 0; mb < 4; mb++)
        #pragma unroll
        for (int nb = 0; nb < 4; nb++)
            #pragma unroll
            for (int e = 0; e < 4; e++) acc[mb][nb][e] = 0.f;

    const int r = tid >> 1, seg = tid & 1;

    issue_chunk(sb, r, seg, rowBase, colBase, 0);
    CP_COMMIT();

    for (int ch = 0; ch < nch; ch++) {
        const int cur = ch & 1;
        if (ch + 1 < nch) {
            issue_chunk(sb + ((ch + 1) & 1) * GSTAGE, r, seg, rowBase, colBase, ch + 1);
            CP_COMMIT();
            CP_WAIT1();
        } else {
            CP_WAIT0();
        }
        __syncthreads();

        const uint32_t aB = sb + cur * GSTAGE + aOff;
        const uint32_t bB = sb + cur * GSTAGE + bOff;
        #pragma unroll
        for (int ks = 0; ks < 32; ks += 16) {
            unsigned bh[4][2], bl[4][2];
            #pragma unroll
            for (int nb = 0; nb < 4; nb++) {
                uint32_t b = bB + nb * (8 * 80) + ks * 2;
                LDM_X2(bh[nb][0], bh[nb][1], b);
                LDM_X2(bl[nb][0], bl[nb][1], b + 10240u);
            }
            #pragma unroll
            for (int mb = 0; mb < 4; mb++) {
                unsigned ah[4], al[4];
                uint32_t a = aB + mb * (16 * 80) + ks * 2;
                LDM_X4(ah[0], ah[1], ah[2], ah[3], a);
                LDM_X4(al[0], al[1], al[2], al[3], a + 10240u);
                #pragma unroll
                for (int nb = 0; nb < 4; nb++) {
                    MMA_BF16(acc[mb][nb], ah, bh[nb]);
                    MMA_BF16(acc[mb][nb], ah, bl[nb]);
                    MMA_BF16(acc[mb][nb], al, bh[nb]);
                }
            }
        }
        __syncthreads();
    }

    const int g = lane >> 2, t4 = lane & 3;
    #pragma unroll
    for (int mb = 0; mb < 4; mb++) {
        int r0 = rowBase + m0 + mb * 16 + g;
        #pragma unroll
        for (int nb = 0; nb < 4; nb++) {
            int c = colBase + n0 + nb * 8 + 2 * t4;
            float b0 = g_bias[c], b1 = g_bias[c + 1];
            *reinterpret_cast<float2*>(&out[(size_t)r0 * C_OUT + c]) =
                make_float2(acc[mb][nb][0] + b0, acc[mb][nb][1] + b1);
            *reinterpret_cast<float2*>(&out[(size_t)(r0 + 8) * C_OUT + c]) =
                make_float2(acc[mb][nb][2] + b0, acc[mb][nb][3] + b1);
        }
    }
}

// ---------------- launcher ----------------
extern "C" void kernel_launch(void* const* d_in, const int* in_sizes, int n_in,
                              void* d_out, int out_size)
{
    const float* x    = (const float*)d_in[0];
    const float* adj1 = (const float*)d_in[1];
    const float* adj2 = (const float*)d_in[2];
    const float* W0a  = (const float*)d_in[3];
    const float* W1a  = (const float*)d_in[4];
    const float* bca  = (const float*)d_in[5];
    const float* W0b  = (const float*)d_in[6];
    const float* W1b  = (const float*)d_in[7];
    const float* bcb  = (const float*)d_in[8];
    const float* Wp   = (const float*)d_in[9];
    const float* bp   = (const float*)d_in[10];
    float* out = (float*)d_out;

    cudaFuncSetAttribute(gemm_mma, cudaFuncAttributeMaxDynamicSharedMemorySize, GSM_TOTAL);

    // L1: row_scan(atomic compaction, round-7 variant) + fold + bias + x pre-split
    mega1<<<8241 + 8192, 256>>>(x, adj1, adj2, W0a, W1a, W0b, W1b, Wp, bca, bcb, bp);
    // L2: sparse propagation (float4 channels, 4 units/block)
    prop_kernel<<<2048, 256>>>(x);
    // L3: fused bf16 tensor-core GEMM, double-buffered cp.async
    gemm_mma<<<dim3(M_TOTAL / 128, C_OUT / 128), 256, GSM_TOTAL>>>(out);
}